// round 11
// baseline (speedup 1.0000x reference)
#include <cuda_runtime.h>
#include <cuda_bf16.h>
#include <cuda_fp16.h>
#include <stdint.h>
#include <math.h>

// Problem constants
#define S_TOK 3072
#define HID 1152
#define NH 16
#define HD 72
#define MLP_DIM 4304
#define MLP_P2 4352           // MLP_DIM padded to multiple of 64 (zeros in pad)
#define QKV_N (3*HID)         // 3456
#define EPS 1e-5f

// ---------------- scratch (allocation-free: __device__ globals, zero-init) ----
__device__ float g_qkv[S_TOK*QKV_N];
__device__ float g_x2[S_TOK*HID];
__device__ unsigned short g_h0h[S_TOK*HID];
__device__ unsigned short g_attnh[S_TOK*HID];
__device__ unsigned short g_h1h[S_TOK*HID];
__device__ unsigned short g_mlph[S_TOK*MLP_P2];     // cols 4304..4351 stay zero
__device__ unsigned short g_wqkvth[QKV_N*HID];
__device__ unsigned short g_woth[HID*HID];
__device__ unsigned short g_w1th[MLP_DIM*HID];
__device__ unsigned short g_w2th[HID*MLP_P2];       // k 4304..4351 stay zero

// ---------------- PTX helpers ----------------
__device__ __forceinline__ uint32_t smem_u32(const void* p) {
    uint32_t a;
    asm("{ .reg .u64 t; cvta.to.shared.u64 t, %1; cvt.u32.u64 %0, t; }"
        : "=r"(a) : "l"(p));
    return a;
}

#define MMA_F16(C, A, B0, B1)                                               \
    asm volatile("mma.sync.aligned.m16n8k16.row.col.f32.f16.f16.f32 "       \
                 "{%0,%1,%2,%3}, {%4,%5,%6,%7}, {%8,%9}, {%0,%1,%2,%3};\n"  \
                 : "+f"((C)[0]), "+f"((C)[1]), "+f"((C)[2]), "+f"((C)[3])   \
                 : "r"((A)[0]), "r"((A)[1]), "r"((A)[2]), "r"((A)[3]),      \
                   "r"(B0), "r"(B1))

#define LDSM_X4(R, a)                                                          \
    asm volatile("ldmatrix.sync.aligned.m8n8.x4.shared.b16 {%0,%1,%2,%3}, [%4];" \
                 : "=r"((R)[0]), "=r"((R)[1]), "=r"((R)[2]), "=r"((R)[3])      \
                 : "r"(a))
#define LDSM_X2(R, a)                                                          \
    asm volatile("ldmatrix.sync.aligned.m8n8.x2.shared.b16 {%0,%1}, [%2];"     \
                 : "=r"((R)[0]), "=r"((R)[1]) : "r"(a))

__device__ __forceinline__ void cp_async16(unsigned dst, const void* src, bool valid) {
    int sz = valid ? 16 : 0;
    asm volatile("cp.async.cg.shared.global [%0], [%1], 16, %2;"
                 :: "r"(dst), "l"(src), "r"(sz));
}
#define CP_COMMIT asm volatile("cp.async.commit_group;")
#define CP_WAIT1  asm volatile("cp.async.wait_group 1;")

__device__ __forceinline__ float gelu_fast(float v) {
    float u = 0.7978845608028654f * (v + 0.044715f * v * v * v);
    return v / (1.0f + __expf(-2.0f * u));
}

// ---------------- LayerNorm (emits fp16 output: feeds GEMM A) --------------
__global__ void ln_kernel(const float* __restrict__ x, const float* __restrict__ g,
                          const float* __restrict__ b, __half* __restrict__ y) {
    __shared__ float row[HID];
    __shared__ float red_s[256], red_ss[256];
    int r = blockIdx.x;
    int tid = threadIdx.x;
    float s = 0.f, ss = 0.f;
    for (int i = tid; i < HID; i += 256) {
        float v = x[(size_t)r*HID + i];
        row[i] = v;
        s += v; ss += v*v;
    }
    red_s[tid] = s; red_ss[tid] = ss;
    __syncthreads();
    for (int o = 128; o > 0; o >>= 1) {
        if (tid < o) { red_s[tid] += red_s[tid+o]; red_ss[tid] += red_ss[tid+o]; }
        __syncthreads();
    }
    float mu = red_s[0] * (1.0f/HID);
    float var = red_ss[0] * (1.0f/HID) - mu*mu;
    float rstd = rsqrtf(var + EPS);
    for (int i = tid; i < HID; i += 256) {
        y[(size_t)r*HID + i] = __float2half_rn((row[i] - mu) * rstd * g[i] + b[i]);
    }
}

// ---------------- weight transpose: [K][N] fp32 -> [N][K(out_ld)] fp16 ------
__global__ void transpose_kernel(const float* __restrict__ in, __half* __restrict__ out,
                                 int K, int N, int out_ld) {
    __shared__ float t[32][33];
    int kb = blockIdx.y*32, nb = blockIdx.x*32;
    int x = threadIdx.x, y = threadIdx.y;   // 32 x 8
#pragma unroll
    for (int i = 0; i < 32; i += 8) {
        int k = kb + y + i, n = nb + x;
        t[y+i][x] = (k < K && n < N) ? in[(size_t)k*N + n] : 0.f;
    }
    __syncthreads();
#pragma unroll
    for (int i = 0; i < 32; i += 8) {
        int n = nb + y + i, k = kb + x;
        if (n < N && k < K) out[(size_t)n*out_ld + k] = __float2half_rn(t[x][y+i]);
    }
}

// ---------------- fp16 GEMM 128x128 (Wo / MLP2) ----------------
#define GBK 64
#define TILE_B (128*128)
#define STAGE_B (2*TILE_B)
#define NSTAGE 3
#define GEMM_SMEM (NSTAGE*STAGE_B)   // 98304

__global__ void __launch_bounds__(256, 2)
hgemm(const __half* __restrict__ A, int ldA,
      const __half* __restrict__ Bt, int ldB,
      const float* __restrict__ bias, const float* __restrict__ residual,
      void* __restrict__ Cv, int ldC, int N, int NIT, int mode) {
    extern __shared__ char smg[];
    unsigned sbase = smem_u32(smg);
    int tid = threadIdx.x, warp = tid >> 5, lane = tid & 31;
    int g = lane >> 2, tg = lane & 3;
    int wy = warp >> 1, wx = warp & 1;
    int m0 = blockIdx.y*128, n0 = blockIdx.x*128;

    float c[2][8][4];
#pragma unroll
    for (int mt = 0; mt < 2; mt++)
#pragma unroll
        for (int nt = 0; nt < 8; nt++)
#pragma unroll
            for (int i = 0; i < 4; i++) c[mt][nt][i] = 0.f;

    auto stage = [&](int it, int buf) {
        int k0 = it*GBK;
        unsigned sA = sbase + buf*STAGE_B;
        unsigned sB = sA + TILE_B;
#pragma unroll
        for (int i = 0; i < 4; i++) {
            int t = tid + i*256;
            int row = t >> 3, ch = t & 7;
            unsigned off = (unsigned)(row*128) + ((unsigned)(ch ^ (row & 7)) << 4);
            cp_async16(sA + off, A + (size_t)(m0+row)*ldA + k0 + ch*8, true);
            int n = n0 + row;
            bool v = (n < N);
            cp_async16(sB + off, Bt + (size_t)(v ? n : 0)*ldB + k0 + ch*8, v);
        }
    };

    stage(0, 0); CP_COMMIT;
    if (NIT > 1) stage(1, 1);
    CP_COMMIT;

    unsigned hi = (unsigned)(lane >> 4);
    unsigned aoff[2], amask[2], boff[4], bmask[4];
#pragma unroll
    for (int mt = 0; mt < 2; mt++) {
        int r = wy*32 + mt*16 + (lane & 15);
        aoff[mt] = (unsigned)(r*128); amask[mt] = (unsigned)(r & 7);
    }
#pragma unroll
    for (int p = 0; p < 4; p++) {
        int r = wx*64 + p*16 + (lane & 15);
        boff[p] = (unsigned)(r*128); bmask[p] = (unsigned)(r & 7);
    }

    for (int it = 0; it < NIT; it++) {
        CP_WAIT1;
        __syncthreads();
        if (it + 2 < NIT) stage(it+2, (it+2)%NSTAGE);
        CP_COMMIT;
        unsigned sA = sbase + (it%NSTAGE)*STAGE_B;
        unsigned sB = sA + TILE_B;
#pragma unroll
        for (int s = 0; s < 4; s++) {
            unsigned ci = (unsigned)(s*2) + hi;
            unsigned a[2][4], b[4][4];
#pragma unroll
            for (int mt = 0; mt < 2; mt++)
                LDSM_X4(a[mt], sA + aoff[mt] + ((ci ^ amask[mt]) << 4));
#pragma unroll
            for (int p = 0; p < 4; p++)
                LDSM_X4(b[p], sB + boff[p] + ((ci ^ bmask[p]) << 4));
#pragma unroll
            for (int mt = 0; mt < 2; mt++)
#pragma unroll
                for (int p = 0; p < 4; p++) {
                    MMA_F16(c[mt][2*p],   a[mt], b[p][0], b[p][2]);
                    MMA_F16(c[mt][2*p+1], a[mt], b[p][1], b[p][3]);
                }
        }
    }

    float* Cf = (float*)Cv;
    __half* Ch = (__half*)Cv;
#pragma unroll
    for (int mt = 0; mt < 2; mt++) {
        int row0 = m0 + wy*32 + mt*16 + g;
#pragma unroll
        for (int nt = 0; nt < 8; nt++) {
            int col = n0 + wx*64 + nt*8 + tg*2;
            if (col >= N) continue;
#pragma unroll
            for (int hf = 0; hf < 2; hf++) {
                int r = row0 + hf*8;
                float v0 = c[mt][nt][hf*2+0] + bias[col];
                float v1 = c[mt][nt][hf*2+1] + bias[col+1];
                if (mode == 1) {
                    v0 += residual[(size_t)r*ldC + col];
                    v1 += residual[(size_t)r*ldC + col + 1];
                    *(float2*)&Cf[(size_t)r*ldC + col] = make_float2(v0, v1);
                } else if (mode == 2) {
                    *(__half2*)&Ch[(size_t)r*ldC + col] =
                        __floats2half2_rn(gelu_fast(v0), gelu_fast(v1));
                } else {
                    *(float2*)&Cf[(size_t)r*ldC + col] = make_float2(v0, v1);
                }
            }
        }
    }
}

// ---------------- fp16 GEMM 256x128, 64x64 warp tiles (QKV / MLP1) ----------
// 8 warps: wy=warp>>1 (4 M-slabs of 64), wx=warp&1 (2 N-slabs of 64)
#define TILE_A2 (256*128)            // bytes per A stage (256 rows x 64 halfs)
#define TILE_B2 (128*128)            // bytes per B stage
#define STAGE_B2 (TILE_A2 + TILE_B2) // 49152
#define GEMM2_SMEM (NSTAGE*STAGE_B2) // 147456

__global__ void __launch_bounds__(256, 1)
hgemm256(const __half* __restrict__ A, int ldA,
         const __half* __restrict__ Bt, int ldB,
         const float* __restrict__ bias,
         void* __restrict__ Cv, int ldC, int N, int NIT, int mode) {
    extern __shared__ char smg[];
    unsigned sbase = smem_u32(smg);
    int tid = threadIdx.x, warp = tid >> 5, lane = tid & 31;
    int g = lane >> 2, tg = lane & 3;
    int wy = warp >> 1, wx = warp & 1;
    int m0 = blockIdx.y*256, n0 = blockIdx.x*128;

    float c[4][8][4];
#pragma unroll
    for (int mt = 0; mt < 4; mt++)
#pragma unroll
        for (int nt = 0; nt < 8; nt++)
#pragma unroll
            for (int i = 0; i < 4; i++) c[mt][nt][i] = 0.f;

    auto stage = [&](int it, int buf) {
        int k0 = it*GBK;
        unsigned sA = sbase + buf*STAGE_B2;
        unsigned sB = sA + TILE_A2;
#pragma unroll
        for (int i = 0; i < 8; i++) {          // A: 256 rows x 8 chunks
            int t = tid + i*256;
            int row = t >> 3, ch = t & 7;
            unsigned off = (unsigned)(row*128) + ((unsigned)(ch ^ (row & 7)) << 4);
            cp_async16(sA + off, A + (size_t)(m0+row)*ldA + k0 + ch*8, true);
        }
#pragma unroll
        for (int i = 0; i < 4; i++) {          // B: 128 rows x 8 chunks
            int t = tid + i*256;
            int row = t >> 3, ch = t & 7;
            unsigned off = (unsigned)(row*128) + ((unsigned)(ch ^ (row & 7)) << 4);
            int n = n0 + row;
            bool v = (n < N);
            cp_async16(sB + off, Bt + (size_t)(v ? n : 0)*ldB + k0 + ch*8, v);
        }
    };

    stage(0, 0); CP_COMMIT;
    if (NIT > 1) stage(1, 1);
    CP_COMMIT;

    unsigned hi = (unsigned)(lane >> 4);
    unsigned aoff[4], amask[4], boff[4], bmask[4];
#pragma unroll
    for (int mt = 0; mt < 4; mt++) {
        int r = wy*64 + mt*16 + (lane & 15);
        aoff[mt] = (unsigned)(r*128); amask[mt] = (unsigned)(r & 7);
    }
#pragma unroll
    for (int p = 0; p < 4; p++) {
        int r = wx*64 + p*16 + (lane & 15);
        boff[p] = (unsigned)(r*128); bmask[p] = (unsigned)(r & 7);
    }

    for (int it = 0; it < NIT; it++) {
        CP_WAIT1;
        __syncthreads();
        if (it + 2 < NIT) stage(it+2, (it+2)%NSTAGE);
        CP_COMMIT;
        unsigned sA = sbase + (it%NSTAGE)*STAGE_B2;
        unsigned sB = sA + TILE_A2;
#pragma unroll
        for (int s = 0; s < 4; s++) {
            unsigned ci = (unsigned)(s*2) + hi;
            unsigned a[4][4], b[4][4];
#pragma unroll
            for (int mt = 0; mt < 4; mt++)
                LDSM_X4(a[mt], sA + aoff[mt] + ((ci ^ amask[mt]) << 4));
#pragma unroll
            for (int p = 0; p < 4; p++)
                LDSM_X4(b[p], sB + boff[p] + ((ci ^ bmask[p]) << 4));
#pragma unroll
            for (int mt = 0; mt < 4; mt++)
#pragma unroll
                for (int p = 0; p < 4; p++) {
                    MMA_F16(c[mt][2*p],   a[mt], b[p][0], b[p][2]);
                    MMA_F16(c[mt][2*p+1], a[mt], b[p][1], b[p][3]);
                }
        }
    }

    float* Cf = (float*)Cv;
    __half* Ch = (__half*)Cv;
#pragma unroll
    for (int mt = 0; mt < 4; mt++) {
        int row0 = m0 + wy*64 + mt*16 + g;
#pragma unroll
        for (int nt = 0; nt < 8; nt++) {
            int col = n0 + wx*64 + nt*8 + tg*2;
            if (col >= N) continue;
#pragma unroll
            for (int hf = 0; hf < 2; hf++) {
                int r = row0 + hf*8;
                float v0 = c[mt][nt][hf*2+0] + bias[col];
                float v1 = c[mt][nt][hf*2+1] + bias[col+1];
                if (mode == 2) {
                    *(__half2*)&Ch[(size_t)r*ldC + col] =
                        __floats2half2_rn(gelu_fast(v0), gelu_fast(v1));
                } else {
                    *(float2*)&Cf[(size_t)r*ldC + col] = make_float2(v0, v1);
                }
            }
        }
    }
}

// ---------------- attention: fp16 MMA, AQ=128, fused RoPE, register softmax --
#define AQ2 128
#define AK2 64
#define QKS_H 88     // Qs/Ks row stride in halfs (80 used, k-pad 72..79 zero)
#define PVS_H 72     // Ps/Vs row stride in halfs (64 used)

__device__ __forceinline__ int seg_of(int t, const int* offs) {
    int s = 0;
#pragma unroll
    for (int i = 1; i <= 6; i++) if (offs[i] <= t) s = i;
    return s;
}

#define ATTN_SMEM ((AQ2*QKS_H + AK2*QKS_H + HD*PVS_H + AQ2*PVS_H)*2 + (64+8)*4)

__global__ void __launch_bounds__(256)
attn2_kernel(const float* __restrict__ qkv, const float* __restrict__ fc,
             const int* __restrict__ offs, __half* __restrict__ out) {
    extern __shared__ char sm[];
    __half* Qh = (__half*)sm;
    __half* Kh = Qh + AQ2*QKS_H;
    __half* Vh = Kh + AK2*QKS_H;
    __half* Ph = Vh + HD*PVS_H;
    int* segk  = (int*)(Ph + AQ2*PVS_H);
    int* soffs = segk + 64;

    unsigned sbase = smem_u32(sm);
    unsigned uQ = sbase;
    unsigned uK = uQ + AQ2*QKS_H*2;
    unsigned uV = uK + AK2*QKS_H*2;
    unsigned uP = uV + HD*PVS_H*2;

    int tid = threadIdx.x, warp = tid >> 5, lane = tid & 31;
    int g = lane >> 2, tg = lane & 3;
    int h = blockIdx.y, q0 = blockIdx.x*AQ2;

    if (tid < 7) soffs[tid] = offs[tid];

    for (int t = tid; t < AQ2 + AK2; t += 256) {
        if (t < AQ2) *(uint4*)&Qh[t*QKS_H + 72] = make_uint4(0,0,0,0);
        else         *(uint4*)&Kh[(t-AQ2)*QKS_H + 72] = make_uint4(0,0,0,0);
    }

    for (int t = tid; t < AQ2*18; t += 256) {
        int row = t/18, ch = t - row*18;
        int tok = q0 + row, d0 = ch*4;
        float4 v = *(const float4*)&qkv[(size_t)tok*QKV_N + h*HD + d0];
        float2 cs0 = *(const float2*)&fc[(size_t)tok*HD + d0];
        float2 cs1 = *(const float2*)&fc[(size_t)tok*HD + d0 + 2];
        __half2 h0 = __floats2half2_rn(v.x*cs0.x - v.y*cs0.y, v.x*cs0.y + v.y*cs0.x);
        __half2 h1 = __floats2half2_rn(v.z*cs1.x - v.w*cs1.y, v.z*cs1.y + v.w*cs1.x);
        *(__half2*)&Qh[row*QKS_H + d0]     = h0;
        *(__half2*)&Qh[row*QKS_H + d0 + 2] = h1;
    }
    __syncthreads();

    int r1 = warp*16 + g, r2 = r1 + 8;
    int sq1 = seg_of(q0 + r1, soffs);
    int sq2 = seg_of(q0 + r2, soffs);

    float m1 = -1e30f, m2 = -1e30f, l1 = 0.f, l2 = 0.f;
    float co[9][4];
#pragma unroll
    for (int nt = 0; nt < 9; nt++)
#pragma unroll
        for (int i = 0; i < 4; i++) co[nt][i] = 0.f;

    unsigned hi = (unsigned)(lane >> 4);
    unsigned offQ = (unsigned)((warp*16 + (lane & 15))*QKS_H*2) + hi*16;
    unsigned offP = (unsigned)((warp*16 + (lane & 15))*PVS_H*2) + hi*16;
    unsigned offK[4], offV[4];
#pragma unroll
    for (int p = 0; p < 4; p++) {
        offK[p] = (unsigned)((p*16 + (lane & 15))*QKS_H*2) + hi*16;
        offV[p] = (unsigned)((p*16 + (lane & 15))*PVS_H*2) + hi*16;
    }
    unsigned offV8 = (unsigned)((64 + (lane & 7))*PVS_H*2) + ((unsigned)((lane >> 3) & 1))*16;

    const float scale = 0.11785113019775793f;   // 1/sqrt(72)

    for (int j0 = 0; j0 < S_TOK; j0 += AK2) {
        __syncthreads();
        for (int t = tid; t < AK2*18; t += 256) {
            int row = t/18, ch = t - row*18;
            int tok = j0 + row, d0 = ch*4;
            float4 v = *(const float4*)&qkv[(size_t)tok*QKV_N + HID + h*HD + d0];
            float2 cs0 = *(const float2*)&fc[(size_t)tok*HD + d0];
            float2 cs1 = *(const float2*)&fc[(size_t)tok*HD + d0 + 2];
            __half2 h0 = __floats2half2_rn(v.x*cs0.x - v.y*cs0.y, v.x*cs0.y + v.y*cs0.x);
            __half2 h1 = __floats2half2_rn(v.z*cs1.x - v.w*cs1.y, v.z*cs1.y + v.w*cs1.x);
            *(__half2*)&Kh[row*QKS_H + d0]     = h0;
            *(__half2*)&Kh[row*QKS_H + d0 + 2] = h1;
        }
        for (int t = tid; t < AK2*18; t += 256) {
            int row = t/18, ch = t - row*18;
            float4 v = *(const float4*)&qkv[(size_t)(j0+row)*QKV_N + 2*HID + h*HD + ch*4];
            int d0 = ch*4;
            Vh[(d0+0)*PVS_H + row] = __float2half_rn(v.x);
            Vh[(d0+1)*PVS_H + row] = __float2half_rn(v.y);
            Vh[(d0+2)*PVS_H + row] = __float2half_rn(v.z);
            Vh[(d0+3)*PVS_H + row] = __float2half_rn(v.w);
        }
        if (tid < 64) segk[tid] = seg_of(j0 + tid, soffs);
        __syncthreads();

        float sc[8][4];
#pragma unroll
        for (int nt = 0; nt < 8; nt++)
#pragma unroll
            for (int i = 0; i < 4; i++) sc[nt][i] = 0.f;
#pragma unroll
        for (int s = 0; s < 5; s++) {
            unsigned a[4], b[4][4];
            LDSM_X4(a, uQ + offQ + s*32);
#pragma unroll
            for (int p = 0; p < 4; p++) LDSM_X4(b[p], uK + offK[p] + s*32);
#pragma unroll
            for (int p = 0; p < 4; p++) {
                MMA_F16(sc[2*p],   a, b[p][0], b[p][2]);
                MMA_F16(sc[2*p+1], a, b[p][1], b[p][3]);
            }
        }
        float mx1 = -1e30f, mx2 = -1e30f;
#pragma unroll
        for (int nt = 0; nt < 8; nt++) {
            int col = nt*8 + tg*2;
            int k0s = segk[col], k1s = segk[col+1];
            sc[nt][0] = sc[nt][0]*scale + (sq1 == k0s ? 1.f : 0.f);
            sc[nt][1] = sc[nt][1]*scale + (sq1 == k1s ? 1.f : 0.f);
            sc[nt][2] = sc[nt][2]*scale + (sq2 == k0s ? 1.f : 0.f);
            sc[nt][3] = sc[nt][3]*scale + (sq2 == k1s ? 1.f : 0.f);
            mx1 = fmaxf(mx1, fmaxf(sc[nt][0], sc[nt][1]));
            mx2 = fmaxf(mx2, fmaxf(sc[nt][2], sc[nt][3]));
        }
        mx1 = fmaxf(mx1, __shfl_xor_sync(0xffffffffu, mx1, 1, 4));
        mx1 = fmaxf(mx1, __shfl_xor_sync(0xffffffffu, mx1, 2, 4));
        mx2 = fmaxf(mx2, __shfl_xor_sync(0xffffffffu, mx2, 1, 4));
        mx2 = fmaxf(mx2, __shfl_xor_sync(0xffffffffu, mx2, 2, 4));
        float mn1 = fmaxf(m1, mx1), mn2 = fmaxf(m2, mx2);
        float f1 = __expf(m1 - mn1), f2 = __expf(m2 - mn2);
        m1 = mn1; m2 = mn2;
        float s1 = 0.f, s2 = 0.f;
#pragma unroll
        for (int nt = 0; nt < 8; nt++) {
            float p0 = __expf(sc[nt][0] - m1);
            float p1 = __expf(sc[nt][1] - m1);
            float p2 = __expf(sc[nt][2] - m2);
            float p3 = __expf(sc[nt][3] - m2);
            s1 += p0 + p1; s2 += p2 + p3;
            int col = nt*8 + tg*2;
            *(__half2*)&Ph[r1*PVS_H + col] = __floats2half2_rn(p0, p1);
            *(__half2*)&Ph[r2*PVS_H + col] = __floats2half2_rn(p2, p3);
        }
        s1 += __shfl_xor_sync(0xffffffffu, s1, 1, 4);
        s1 += __shfl_xor_sync(0xffffffffu, s1, 2, 4);
        s2 += __shfl_xor_sync(0xffffffffu, s2, 1, 4);
        s2 += __shfl_xor_sync(0xffffffffu, s2, 2, 4);
        l1 = l1*f1 + s1; l2 = l2*f2 + s2;
#pragma unroll
        for (int nt = 0; nt < 9; nt++) {
            co[nt][0] *= f1; co[nt][1] *= f1;
            co[nt][2] *= f2; co[nt][3] *= f2;
        }
        __syncthreads();
#pragma unroll
        for (int s = 0; s < 4; s++) {
            unsigned a[4], b[4][4], b8[2];
            LDSM_X4(a, uP + offP + s*32);
#pragma unroll
            for (int p = 0; p < 4; p++) LDSM_X4(b[p], uV + offV[p] + s*32);
            LDSM_X2(b8, uV + offV8 + s*32);
#pragma unroll
            for (int p = 0; p < 4; p++) {
                MMA_F16(co[2*p],   a, b[p][0], b[p][2]);
                MMA_F16(co[2*p+1], a, b[p][1], b[p][3]);
            }
            MMA_F16(co[8], a, b8[0], b8[1]);
        }
    }

    float i1 = 1.f/l1, i2 = 1.f/l2;
#pragma unroll
    for (int nt = 0; nt < 9; nt++) {
        int d0 = nt*8 + tg*2;
        *(__half2*)&out[(size_t)(q0+r1)*HID + h*HD + d0] =
            __floats2half2_rn(co[nt][0]*i1, co[nt][1]*i1);
        *(__half2*)&out[(size_t)(q0+r2)*HID + h*HD + d0] =
            __floats2half2_rn(co[nt][2]*i2, co[nt][3]*i2);
    }
}

// ---------------- launch ----------------
extern "C" void kernel_launch(void* const* d_in, const int* in_sizes, int n_in,
                              void* d_out, int out_size) {
    const float* x      = (const float*)d_in[0];
    const int*   offs   = (const int*)  d_in[1];
    const float* fc     = (const float*)d_in[2];
    const float* ln0_g  = (const float*)d_in[3];
    const float* ln0_b  = (const float*)d_in[4];
    const float* wqkv_w = (const float*)d_in[5];
    const float* wqkv_b = (const float*)d_in[6];
    const float* wo_w   = (const float*)d_in[7];
    const float* wo_b   = (const float*)d_in[8];
    const float* ln1_g  = (const float*)d_in[9];
    const float* ln1_b  = (const float*)d_in[10];
    const float* w1     = (const float*)d_in[11];
    const float* b1     = (const float*)d_in[12];
    const float* w2     = (const float*)d_in[13];
    const float* b2     = (const float*)d_in[14];
    float* out = (float*)d_out;

    float *qkv, *x2;
    __half *h0h, *attnh, *h1h, *mlph, *wqkvth, *woth, *w1th, *w2th;
    cudaGetSymbolAddress((void**)&qkv,    g_qkv);
    cudaGetSymbolAddress((void**)&x2,     g_x2);
    cudaGetSymbolAddress((void**)&h0h,    g_h0h);
    cudaGetSymbolAddress((void**)&attnh,  g_attnh);
    cudaGetSymbolAddress((void**)&h1h,    g_h1h);
    cudaGetSymbolAddress((void**)&mlph,   g_mlph);
    cudaGetSymbolAddress((void**)&wqkvth, g_wqkvth);
    cudaGetSymbolAddress((void**)&woth,   g_woth);
    cudaGetSymbolAddress((void**)&w1th,   g_w1th);
    cudaGetSymbolAddress((void**)&w2th,   g_w2th);

    cudaFuncSetAttribute(hgemm, cudaFuncAttributeMaxDynamicSharedMemorySize, GEMM_SMEM);
    cudaFuncSetAttribute(hgemm256, cudaFuncAttributeMaxDynamicSharedMemorySize, GEMM2_SMEM);
    cudaFuncSetAttribute(attn2_kernel, cudaFuncAttributeMaxDynamicSharedMemorySize, ATTN_SMEM);

    // 0. transpose weights -> [N][K] fp16
    transpose_kernel<<<dim3((QKV_N+31)/32, (HID+31)/32), dim3(32,8)>>>(wqkv_w, wqkvth, HID, QKV_N, HID);
    transpose_kernel<<<dim3((HID+31)/32, (HID+31)/32),   dim3(32,8)>>>(wo_w,   woth,   HID, HID,   HID);
    transpose_kernel<<<dim3((MLP_DIM+31)/32, (HID+31)/32), dim3(32,8)>>>(w1, w1th, HID, MLP_DIM, HID);
    transpose_kernel<<<dim3((HID+31)/32, (MLP_DIM+31)/32), dim3(32,8)>>>(w2, w2th, MLP_DIM, HID, MLP_P2);

    // 1. LN0 -> fp16
    ln_kernel<<<S_TOK, 256>>>(x, ln0_g, ln0_b, h0h);
    // 2. QKV = h0 @ wqkv + b  (fp32 out; rope at attention staging)  [256-tile]
    hgemm256<<<dim3(QKV_N/128, S_TOK/256), 256, GEMM2_SMEM>>>(
        h0h, HID, wqkvth, HID, wqkv_b, qkv, QKV_N, QKV_N, HID/GBK, 0);
    // 3. attention (fused rope) -> fp16
    attn2_kernel<<<dim3(S_TOK/AQ2, NH), 256, ATTN_SMEM>>>(qkv, fc, offs, attnh);
    // 4. x2 = x + attn @ wo + b  (fp32 out)
    hgemm<<<dim3(HID/128, S_TOK/128), 256, GEMM_SMEM>>>(
        attnh, HID, woth, HID, wo_b, x, x2, HID, HID, HID/GBK, 1);
    // 5. LN1 -> fp16
    ln_kernel<<<S_TOK, 256>>>(x2, ln1_g, ln1_b, h1h);
    // 6. mlp = gelu(h1 @ w1 + b1) -> fp16 (padded ldC)  [256-tile]
    hgemm256<<<dim3((MLP_DIM+127)/128, S_TOK/256), 256, GEMM2_SMEM>>>(
        h1h, HID, w1th, HID, b1, mlph, MLP_P2, MLP_DIM, HID/GBK, 2);
    // 7. out = x2 + mlp @ w2 + b2  (K padded to 4352 with zeros)
    hgemm<<<dim3(HID/128, S_TOK/128), 256, GEMM_SMEM>>>(
        mlph, MLP_P2, w2th, MLP_P2, b2, x2, out, HID, HID, MLP_P2/GBK, 1);
}

// round 12
// speedup vs baseline: 1.0964x; 1.0964x over previous
#include <cuda_runtime.h>
#include <cuda_bf16.h>
#include <cuda_fp16.h>
#include <stdint.h>
#include <math.h>

// Problem constants
#define S_TOK 3072
#define HID 1152
#define NH 16
#define HD 72
#define MLP_DIM 4304
#define MLP_P2 4352           // MLP_DIM padded to multiple of 64 (zeros in pad)
#define QKV_N (3*HID)         // 3456
#define EPS 1e-5f

// ---------------- scratch (allocation-free: __device__ globals, zero-init) ----
__device__ float g_x2[S_TOK*HID];
__device__ unsigned short g_qkvh[S_TOK*QKV_N];      // fp16 qkv
__device__ unsigned short g_h0h[S_TOK*HID];
__device__ unsigned short g_attnh[S_TOK*HID];
__device__ unsigned short g_h1h[S_TOK*HID];
__device__ unsigned short g_mlph[S_TOK*MLP_P2];     // cols 4304..4351 stay zero
__device__ unsigned short g_wqkvth[QKV_N*HID];
__device__ unsigned short g_woth[HID*HID];
__device__ unsigned short g_w1th[MLP_DIM*HID];
__device__ unsigned short g_w2th[HID*MLP_P2];       // k 4304..4351 stay zero

// ---------------- PTX helpers ----------------
__device__ __forceinline__ uint32_t smem_u32(const void* p) {
    uint32_t a;
    asm("{ .reg .u64 t; cvta.to.shared.u64 t, %1; cvt.u32.u64 %0, t; }"
        : "=r"(a) : "l"(p));
    return a;
}

#define MMA_F16(C, A, B0, B1)                                               \
    asm volatile("mma.sync.aligned.m16n8k16.row.col.f32.f16.f16.f32 "       \
                 "{%0,%1,%2,%3}, {%4,%5,%6,%7}, {%8,%9}, {%0,%1,%2,%3};\n"  \
                 : "+f"((C)[0]), "+f"((C)[1]), "+f"((C)[2]), "+f"((C)[3])   \
                 : "r"((A)[0]), "r"((A)[1]), "r"((A)[2]), "r"((A)[3]),      \
                   "r"(B0), "r"(B1))

#define LDSM_X4(R, a)                                                          \
    asm volatile("ldmatrix.sync.aligned.m8n8.x4.shared.b16 {%0,%1,%2,%3}, [%4];" \
                 : "=r"((R)[0]), "=r"((R)[1]), "=r"((R)[2]), "=r"((R)[3])      \
                 : "r"(a))
#define LDSM_X2(R, a)                                                          \
    asm volatile("ldmatrix.sync.aligned.m8n8.x2.shared.b16 {%0,%1}, [%2];"     \
                 : "=r"((R)[0]), "=r"((R)[1]) : "r"(a))

__device__ __forceinline__ void cp_async16(unsigned dst, const void* src, bool valid) {
    int sz = valid ? 16 : 0;
    asm volatile("cp.async.cg.shared.global [%0], [%1], 16, %2;"
                 :: "r"(dst), "l"(src), "r"(sz));
}
#define CP_COMMIT asm volatile("cp.async.commit_group;")
#define CP_WAIT1  asm volatile("cp.async.wait_group 1;")

__device__ __forceinline__ float gelu_fast(float v) {
    float u = 0.7978845608028654f * (v + 0.044715f * v * v * v);
    return v / (1.0f + __expf(-2.0f * u));
}

// ---------------- LayerNorm (emits fp16 output: feeds GEMM A) --------------
__global__ void ln_kernel(const float* __restrict__ x, const float* __restrict__ g,
                          const float* __restrict__ b, __half* __restrict__ y) {
    __shared__ float row[HID];
    __shared__ float red_s[256], red_ss[256];
    int r = blockIdx.x;
    int tid = threadIdx.x;
    float s = 0.f, ss = 0.f;
    for (int i = tid; i < HID; i += 256) {
        float v = x[(size_t)r*HID + i];
        row[i] = v;
        s += v; ss += v*v;
    }
    red_s[tid] = s; red_ss[tid] = ss;
    __syncthreads();
    for (int o = 128; o > 0; o >>= 1) {
        if (tid < o) { red_s[tid] += red_s[tid+o]; red_ss[tid] += red_ss[tid+o]; }
        __syncthreads();
    }
    float mu = red_s[0] * (1.0f/HID);
    float var = red_ss[0] * (1.0f/HID) - mu*mu;
    float rstd = rsqrtf(var + EPS);
    for (int i = tid; i < HID; i += 256) {
        y[(size_t)r*HID + i] = __float2half_rn((row[i] - mu) * rstd * g[i] + b[i]);
    }
}

// ---------------- weight transpose: [K][N] fp32 -> [N][K(out_ld)] fp16 ------
__global__ void transpose_kernel(const float* __restrict__ in, __half* __restrict__ out,
                                 int K, int N, int out_ld) {
    __shared__ float t[32][33];
    int kb = blockIdx.y*32, nb = blockIdx.x*32;
    int x = threadIdx.x, y = threadIdx.y;   // 32 x 8
#pragma unroll
    for (int i = 0; i < 32; i += 8) {
        int k = kb + y + i, n = nb + x;
        t[y+i][x] = (k < K && n < N) ? in[(size_t)k*N + n] : 0.f;
    }
    __syncthreads();
#pragma unroll
    for (int i = 0; i < 32; i += 8) {
        int n = nb + y + i, k = kb + x;
        if (n < N && k < K) out[(size_t)n*out_ld + k] = __float2half_rn(t[x][y+i]);
    }
}

// ---------------- fp16 GEMM 128x128, 3-stage cp.async (all GEMMs) -----------
// mode 0: bias fp32 out; 1: bias+residual fp32 out; 2: bias+gelu fp16 out;
// mode 3: bias fp16 out
#define GBK 64
#define TILE_B (128*128)
#define STAGE_B (2*TILE_B)
#define NSTAGE 3
#define GEMM_SMEM (NSTAGE*STAGE_B)   // 98304

__global__ void __launch_bounds__(256, 2)
hgemm(const __half* __restrict__ A, int ldA,
      const __half* __restrict__ Bt, int ldB,
      const float* __restrict__ bias, const float* __restrict__ residual,
      void* __restrict__ Cv, int ldC, int N, int NIT, int mode) {
    extern __shared__ char smg[];
    unsigned sbase = smem_u32(smg);
    int tid = threadIdx.x, warp = tid >> 5, lane = tid & 31;
    int g = lane >> 2, tg = lane & 3;
    int wy = warp >> 1, wx = warp & 1;
    int m0 = blockIdx.y*128, n0 = blockIdx.x*128;

    float c[2][8][4];
#pragma unroll
    for (int mt = 0; mt < 2; mt++)
#pragma unroll
        for (int nt = 0; nt < 8; nt++)
#pragma unroll
            for (int i = 0; i < 4; i++) c[mt][nt][i] = 0.f;

    auto stage = [&](int it, int buf) {
        int k0 = it*GBK;
        unsigned sA = sbase + buf*STAGE_B;
        unsigned sB = sA + TILE_B;
#pragma unroll
        for (int i = 0; i < 4; i++) {
            int t = tid + i*256;
            int row = t >> 3, ch = t & 7;
            unsigned off = (unsigned)(row*128) + ((unsigned)(ch ^ (row & 7)) << 4);
            cp_async16(sA + off, A + (size_t)(m0+row)*ldA + k0 + ch*8, true);
            int n = n0 + row;
            bool v = (n < N);
            cp_async16(sB + off, Bt + (size_t)(v ? n : 0)*ldB + k0 + ch*8, v);
        }
    };

    stage(0, 0); CP_COMMIT;
    if (NIT > 1) stage(1, 1);
    CP_COMMIT;

    unsigned hi = (unsigned)(lane >> 4);
    unsigned aoff[2], amask[2], boff[4], bmask[4];
#pragma unroll
    for (int mt = 0; mt < 2; mt++) {
        int r = wy*32 + mt*16 + (lane & 15);
        aoff[mt] = (unsigned)(r*128); amask[mt] = (unsigned)(r & 7);
    }
#pragma unroll
    for (int p = 0; p < 4; p++) {
        int r = wx*64 + p*16 + (lane & 15);
        boff[p] = (unsigned)(r*128); bmask[p] = (unsigned)(r & 7);
    }

    for (int it = 0; it < NIT; it++) {
        CP_WAIT1;
        __syncthreads();
        if (it + 2 < NIT) stage(it+2, (it+2)%NSTAGE);
        CP_COMMIT;
        unsigned sA = sbase + (it%NSTAGE)*STAGE_B;
        unsigned sB = sA + TILE_B;
#pragma unroll
        for (int s = 0; s < 4; s++) {
            unsigned ci = (unsigned)(s*2) + hi;
            unsigned a[2][4], b[4][4];
#pragma unroll
            for (int mt = 0; mt < 2; mt++)
                LDSM_X4(a[mt], sA + aoff[mt] + ((ci ^ amask[mt]) << 4));
#pragma unroll
            for (int p = 0; p < 4; p++)
                LDSM_X4(b[p], sB + boff[p] + ((ci ^ bmask[p]) << 4));
#pragma unroll
            for (int mt = 0; mt < 2; mt++)
#pragma unroll
                for (int p = 0; p < 4; p++) {
                    MMA_F16(c[mt][2*p],   a[mt], b[p][0], b[p][2]);
                    MMA_F16(c[mt][2*p+1], a[mt], b[p][1], b[p][3]);
                }
        }
    }

    float* Cf = (float*)Cv;
    __half* Ch = (__half*)Cv;
#pragma unroll
    for (int mt = 0; mt < 2; mt++) {
        int row0 = m0 + wy*32 + mt*16 + g;
#pragma unroll
        for (int nt = 0; nt < 8; nt++) {
            int col = n0 + wx*64 + nt*8 + tg*2;
            if (col >= N) continue;
#pragma unroll
            for (int hf = 0; hf < 2; hf++) {
                int r = row0 + hf*8;
                float v0 = c[mt][nt][hf*2+0] + bias[col];
                float v1 = c[mt][nt][hf*2+1] + bias[col+1];
                if (mode == 1) {
                    v0 += residual[(size_t)r*ldC + col];
                    v1 += residual[(size_t)r*ldC + col + 1];
                    *(float2*)&Cf[(size_t)r*ldC + col] = make_float2(v0, v1);
                } else if (mode == 2) {
                    *(__half2*)&Ch[(size_t)r*ldC + col] =
                        __floats2half2_rn(gelu_fast(v0), gelu_fast(v1));
                } else if (mode == 3) {
                    *(__half2*)&Ch[(size_t)r*ldC + col] = __floats2half2_rn(v0, v1);
                } else {
                    *(float2*)&Cf[(size_t)r*ldC + col] = make_float2(v0, v1);
                }
            }
        }
    }
}

// ---------------- attention: fp16 MMA, AQ=128, fused RoPE, register softmax --
#define AQ2 128
#define AK2 64
#define QKS_H 88     // Qs/Ks row stride in halfs (80 used, k-pad 72..79 zero)
#define PVS_H 72     // Ps/Vs row stride in halfs (64 used)

__device__ __forceinline__ int seg_of(int t, const int* offs) {
    int s = 0;
#pragma unroll
    for (int i = 1; i <= 6; i++) if (offs[i] <= t) s = i;
    return s;
}

#define ATTN_SMEM ((AQ2*QKS_H + AK2*QKS_H + HD*PVS_H + AQ2*PVS_H)*2 + (64+8)*4)

__global__ void __launch_bounds__(256)
attn2_kernel(const __half* __restrict__ qkv, const float* __restrict__ fc,
             const int* __restrict__ offs, __half* __restrict__ out) {
    extern __shared__ char sm[];
    __half* Qh = (__half*)sm;
    __half* Kh = Qh + AQ2*QKS_H;
    __half* Vh = Kh + AK2*QKS_H;
    __half* Ph = Vh + HD*PVS_H;
    int* segk  = (int*)(Ph + AQ2*PVS_H);
    int* soffs = segk + 64;

    unsigned sbase = smem_u32(sm);
    unsigned uQ = sbase;
    unsigned uK = uQ + AQ2*QKS_H*2;
    unsigned uV = uK + AK2*QKS_H*2;
    unsigned uP = uV + HD*PVS_H*2;

    int tid = threadIdx.x, warp = tid >> 5, lane = tid & 31;
    int g = lane >> 2, tg = lane & 3;
    int h = blockIdx.y, q0 = blockIdx.x*AQ2;

    if (tid < 7) soffs[tid] = offs[tid];

    // zero k-pad halfs 72..79 of Qs (128 rows) and Ks (64 rows)
    for (int t = tid; t < AQ2 + AK2; t += 256) {
        if (t < AQ2) *(uint4*)&Qh[t*QKS_H + 72] = make_uint4(0,0,0,0);
        else         *(uint4*)&Kh[(t-AQ2)*QKS_H + 72] = make_uint4(0,0,0,0);
    }

    // stage Q with fused RoPE (fp16 source, fp32 trig math)
    for (int t = tid; t < AQ2*9; t += 256) {
        int row = t/9, ch = t - row*9;
        int tok = q0 + row, d0 = ch*8;
        uint4 raw = *(const uint4*)&qkv[(size_t)tok*QKV_N + h*HD + d0];
        float4 cA = *(const float4*)&fc[(size_t)tok*HD + d0];
        float4 cB = *(const float4*)&fc[(size_t)tok*HD + d0 + 4];
        __half2 p0 = *(__half2*)&raw.x, p1 = *(__half2*)&raw.y;
        __half2 p2 = *(__half2*)&raw.z, p3 = *(__half2*)&raw.w;
        float2 f0 = __half22float2(p0), f1 = __half22float2(p1);
        float2 f2 = __half22float2(p2), f3 = __half22float2(p3);
        uint4 o;
        *(__half2*)&o.x = __floats2half2_rn(f0.x*cA.x - f0.y*cA.y, f0.x*cA.y + f0.y*cA.x);
        *(__half2*)&o.y = __floats2half2_rn(f1.x*cA.z - f1.y*cA.w, f1.x*cA.w + f1.y*cA.z);
        *(__half2*)&o.z = __floats2half2_rn(f2.x*cB.x - f2.y*cB.y, f2.x*cB.y + f2.y*cB.x);
        *(__half2*)&o.w = __floats2half2_rn(f3.x*cB.z - f3.y*cB.w, f3.x*cB.w + f3.y*cB.z);
        *(uint4*)&Qh[row*QKS_H + d0] = o;
    }
    __syncthreads();

    int r1 = warp*16 + g, r2 = r1 + 8;
    int sq1 = seg_of(q0 + r1, soffs);
    int sq2 = seg_of(q0 + r2, soffs);

    float m1 = -1e30f, m2 = -1e30f, l1 = 0.f, l2 = 0.f;
    float co[9][4];
#pragma unroll
    for (int nt = 0; nt < 9; nt++)
#pragma unroll
        for (int i = 0; i < 4; i++) co[nt][i] = 0.f;

    unsigned hi = (unsigned)(lane >> 4);
    unsigned offQ = (unsigned)((warp*16 + (lane & 15))*QKS_H*2) + hi*16;
    unsigned offP = (unsigned)((warp*16 + (lane & 15))*PVS_H*2) + hi*16;
    unsigned offK[4], offV[4];
#pragma unroll
    for (int p = 0; p < 4; p++) {
        offK[p] = (unsigned)((p*16 + (lane & 15))*QKS_H*2) + hi*16;
        offV[p] = (unsigned)((p*16 + (lane & 15))*PVS_H*2) + hi*16;
    }
    unsigned offV8 = (unsigned)((64 + (lane & 7))*PVS_H*2) + ((unsigned)((lane >> 3) & 1))*16;

    const float scale = 0.11785113019775793f;   // 1/sqrt(72)

    for (int j0 = 0; j0 < S_TOK; j0 += AK2) {
        __syncthreads();
        // stage K (rope) and V transposed [d][tok], both from fp16 qkv
        for (int t = tid; t < AK2*9; t += 256) {
            int row = t/9, ch = t - row*9;
            int tok = j0 + row, d0 = ch*8;
            uint4 raw = *(const uint4*)&qkv[(size_t)tok*QKV_N + HID + h*HD + d0];
            float4 cA = *(const float4*)&fc[(size_t)tok*HD + d0];
            float4 cB = *(const float4*)&fc[(size_t)tok*HD + d0 + 4];
            __half2 p0 = *(__half2*)&raw.x, p1 = *(__half2*)&raw.y;
            __half2 p2 = *(__half2*)&raw.z, p3 = *(__half2*)&raw.w;
            float2 f0 = __half22float2(p0), f1 = __half22float2(p1);
            float2 f2 = __half22float2(p2), f3 = __half22float2(p3);
            uint4 o;
            *(__half2*)&o.x = __floats2half2_rn(f0.x*cA.x - f0.y*cA.y, f0.x*cA.y + f0.y*cA.x);
            *(__half2*)&o.y = __floats2half2_rn(f1.x*cA.z - f1.y*cA.w, f1.x*cA.w + f1.y*cA.z);
            *(__half2*)&o.z = __floats2half2_rn(f2.x*cB.x - f2.y*cB.y, f2.x*cB.y + f2.y*cB.x);
            *(__half2*)&o.w = __floats2half2_rn(f3.x*cB.z - f3.y*cB.w, f3.x*cB.w + f3.y*cB.z);
            *(uint4*)&Kh[row*QKS_H + d0] = o;
        }
        for (int t = tid; t < AK2*9; t += 256) {
            int row = t/9, ch = t - row*9;
            int d0 = ch*8;
            uint4 raw = *(const uint4*)&qkv[(size_t)(j0+row)*QKV_N + 2*HID + h*HD + d0];
            const __half* hp = (const __half*)&raw;
#pragma unroll
            for (int i = 0; i < 8; i++)
                Vh[(d0+i)*PVS_H + row] = hp[i];
        }
        if (tid < 64) segk[tid] = seg_of(j0 + tid, soffs);
        __syncthreads();

        float sc[8][4];
#pragma unroll
        for (int nt = 0; nt < 8; nt++)
#pragma unroll
            for (int i = 0; i < 4; i++) sc[nt][i] = 0.f;
#pragma unroll
        for (int s = 0; s < 5; s++) {
            unsigned a[4], b[4][4];
            LDSM_X4(a, uQ + offQ + s*32);
#pragma unroll
            for (int p = 0; p < 4; p++) LDSM_X4(b[p], uK + offK[p] + s*32);
#pragma unroll
            for (int p = 0; p < 4; p++) {
                MMA_F16(sc[2*p],   a, b[p][0], b[p][2]);
                MMA_F16(sc[2*p+1], a, b[p][1], b[p][3]);
            }
        }
        float mx1 = -1e30f, mx2 = -1e30f;
#pragma unroll
        for (int nt = 0; nt < 8; nt++) {
            int col = nt*8 + tg*2;
            int k0s = segk[col], k1s = segk[col+1];
            sc[nt][0] = sc[nt][0]*scale + (sq1 == k0s ? 1.f : 0.f);
            sc[nt][1] = sc[nt][1]*scale + (sq1 == k1s ? 1.f : 0.f);
            sc[nt][2] = sc[nt][2]*scale + (sq2 == k0s ? 1.f : 0.f);
            sc[nt][3] = sc[nt][3]*scale + (sq2 == k1s ? 1.f : 0.f);
            mx1 = fmaxf(mx1, fmaxf(sc[nt][0], sc[nt][1]));
            mx2 = fmaxf(mx2, fmaxf(sc[nt][2], sc[nt][3]));
        }
        mx1 = fmaxf(mx1, __shfl_xor_sync(0xffffffffu, mx1, 1, 4));
        mx1 = fmaxf(mx1, __shfl_xor_sync(0xffffffffu, mx1, 2, 4));
        mx2 = fmaxf(mx2, __shfl_xor_sync(0xffffffffu, mx2, 1, 4));
        mx2 = fmaxf(mx2, __shfl_xor_sync(0xffffffffu, mx2, 2, 4));
        float mn1 = fmaxf(m1, mx1), mn2 = fmaxf(m2, mx2);
        float f1 = __expf(m1 - mn1), f2 = __expf(m2 - mn2);
        m1 = mn1; m2 = mn2;
        float s1 = 0.f, s2 = 0.f;
#pragma unroll
        for (int nt = 0; nt < 8; nt++) {
            float p0 = __expf(sc[nt][0] - m1);
            float p1 = __expf(sc[nt][1] - m1);
            float p2 = __expf(sc[nt][2] - m2);
            float p3 = __expf(sc[nt][3] - m2);
            s1 += p0 + p1; s2 += p2 + p3;
            int col = nt*8 + tg*2;
            *(__half2*)&Ph[r1*PVS_H + col] = __floats2half2_rn(p0, p1);
            *(__half2*)&Ph[r2*PVS_H + col] = __floats2half2_rn(p2, p3);
        }
        s1 += __shfl_xor_sync(0xffffffffu, s1, 1, 4);
        s1 += __shfl_xor_sync(0xffffffffu, s1, 2, 4);
        s2 += __shfl_xor_sync(0xffffffffu, s2, 1, 4);
        s2 += __shfl_xor_sync(0xffffffffu, s2, 2, 4);
        l1 = l1*f1 + s1; l2 = l2*f2 + s2;
#pragma unroll
        for (int nt = 0; nt < 9; nt++) {
            co[nt][0] *= f1; co[nt][1] *= f1;
            co[nt][2] *= f2; co[nt][3] *= f2;
        }
        __syncthreads();
#pragma unroll
        for (int s = 0; s < 4; s++) {
            unsigned a[4], b[4][4], b8[2];
            LDSM_X4(a, uP + offP + s*32);
#pragma unroll
            for (int p = 0; p < 4; p++) LDSM_X4(b[p], uV + offV[p] + s*32);
            LDSM_X2(b8, uV + offV8 + s*32);
#pragma unroll
            for (int p = 0; p < 4; p++) {
                MMA_F16(co[2*p],   a, b[p][0], b[p][2]);
                MMA_F16(co[2*p+1], a, b[p][1], b[p][3]);
            }
            MMA_F16(co[8], a, b8[0], b8[1]);
        }
    }

    float i1 = 1.f/l1, i2 = 1.f/l2;
#pragma unroll
    for (int nt = 0; nt < 9; nt++) {
        int d0 = nt*8 + tg*2;
        *(__half2*)&out[(size_t)(q0+r1)*HID + h*HD + d0] =
            __floats2half2_rn(co[nt][0]*i1, co[nt][1]*i1);
        *(__half2*)&out[(size_t)(q0+r2)*HID + h*HD + d0] =
            __floats2half2_rn(co[nt][2]*i2, co[nt][3]*i2);
    }
}

// ---------------- launch ----------------
extern "C" void kernel_launch(void* const* d_in, const int* in_sizes, int n_in,
                              void* d_out, int out_size) {
    const float* x      = (const float*)d_in[0];
    const int*   offs   = (const int*)  d_in[1];
    const float* fc     = (const float*)d_in[2];
    const float* ln0_g  = (const float*)d_in[3];
    const float* ln0_b  = (const float*)d_in[4];
    const float* wqkv_w = (const float*)d_in[5];
    const float* wqkv_b = (const float*)d_in[6];
    const float* wo_w   = (const float*)d_in[7];
    const float* wo_b   = (const float*)d_in[8];
    const float* ln1_g  = (const float*)d_in[9];
    const float* ln1_b  = (const float*)d_in[10];
    const float* w1     = (const float*)d_in[11];
    const float* b1     = (const float*)d_in[12];
    const float* w2     = (const float*)d_in[13];
    const float* b2     = (const float*)d_in[14];
    float* out = (float*)d_out;

    float *x2;
    __half *qkvh, *h0h, *attnh, *h1h, *mlph, *wqkvth, *woth, *w1th, *w2th;
    cudaGetSymbolAddress((void**)&x2,     g_x2);
    cudaGetSymbolAddress((void**)&qkvh,   g_qkvh);
    cudaGetSymbolAddress((void**)&h0h,    g_h0h);
    cudaGetSymbolAddress((void**)&attnh,  g_attnh);
    cudaGetSymbolAddress((void**)&h1h,    g_h1h);
    cudaGetSymbolAddress((void**)&mlph,   g_mlph);
    cudaGetSymbolAddress((void**)&wqkvth, g_wqkvth);
    cudaGetSymbolAddress((void**)&woth,   g_woth);
    cudaGetSymbolAddress((void**)&w1th,   g_w1th);
    cudaGetSymbolAddress((void**)&w2th,   g_w2th);

    cudaFuncSetAttribute(hgemm, cudaFuncAttributeMaxDynamicSharedMemorySize, GEMM_SMEM);
    cudaFuncSetAttribute(attn2_kernel, cudaFuncAttributeMaxDynamicSharedMemorySize, ATTN_SMEM);

    // 0. transpose weights -> [N][K] fp16
    transpose_kernel<<<dim3((QKV_N+31)/32, (HID+31)/32), dim3(32,8)>>>(wqkv_w, wqkvth, HID, QKV_N, HID);
    transpose_kernel<<<dim3((HID+31)/32, (HID+31)/32),   dim3(32,8)>>>(wo_w,   woth,   HID, HID,   HID);
    transpose_kernel<<<dim3((MLP_DIM+31)/32, (HID+31)/32), dim3(32,8)>>>(w1, w1th, HID, MLP_DIM, HID);
    transpose_kernel<<<dim3((HID+31)/32, (MLP_DIM+31)/32), dim3(32,8)>>>(w2, w2th, MLP_DIM, HID, MLP_P2);

    // 1. LN0 -> fp16
    ln_kernel<<<S_TOK, 256>>>(x, ln0_g, ln0_b, h0h);
    // 2. QKV = h0 @ wqkv + b  -> fp16 (rope at attention staging)
    hgemm<<<dim3(QKV_N/128, S_TOK/128), 256, GEMM_SMEM>>>(
        h0h, HID, wqkvth, HID, wqkv_b, nullptr, qkvh, QKV_N, QKV_N, HID/GBK, 3);
    // 3. attention (fused rope) -> fp16
    attn2_kernel<<<dim3(S_TOK/AQ2, NH), 256, ATTN_SMEM>>>(qkvh, fc, offs, attnh);
    // 4. x2 = x + attn @ wo + b  (fp32 out)
    hgemm<<<dim3(HID/128, S_TOK/128), 256, GEMM_SMEM>>>(
        attnh, HID, woth, HID, wo_b, x, x2, HID, HID, HID/GBK, 1);
    // 5. LN1 -> fp16
    ln_kernel<<<S_TOK, 256>>>(x2, ln1_g, ln1_b, h1h);
    // 6. mlp = gelu(h1 @ w1 + b1) -> fp16 (padded ldC)
    hgemm<<<dim3((MLP_DIM+127)/128, S_TOK/128), 256, GEMM_SMEM>>>(
        h1h, HID, w1th, HID, b1, nullptr, mlph, MLP_P2, MLP_DIM, HID/GBK, 2);
    // 7. out = x2 + mlp @ w2 + b2  (K padded to 4352 with zeros)
    hgemm<<<dim3(HID/128, S_TOK/128), 256, GEMM_SMEM>>>(
        mlph, MLP_P2, w2th, MLP_P2, b2, x2, out, HID, HID, MLP_P2/GBK, 1);
}

// round 13
// speedup vs baseline: 1.4361x; 1.3098x over previous
#include <cuda_runtime.h>
#include <cuda_bf16.h>
#include <cuda_fp16.h>
#include <stdint.h>
#include <math.h>

// Problem constants
#define S_TOK 3072
#define HID 1152
#define NH 16
#define HD 72
#define MLP_DIM 4304
#define MLP_P2 4352           // MLP_DIM padded to multiple of 64 (zeros in pad)
#define QKV_N (3*HID)         // 3456
#define EPS 1e-5f

// ---------------- scratch (allocation-free: __device__ globals, zero-init) ----
__device__ float g_x2[S_TOK*HID];
__device__ unsigned short g_qkvh[S_TOK*QKV_N];      // fp16 qkv (pre-rope)
__device__ unsigned short g_Qr[NH*S_TOK*80];        // rope'd Q, [h][tok][80]
__device__ unsigned short g_Kr[NH*S_TOK*80];        // rope'd K, [h][tok][80]
__device__ unsigned short g_Vt[NH*HD*S_TOK];        // V^T,     [h][d][tok]
__device__ unsigned short g_h0h[S_TOK*HID];
__device__ unsigned short g_attnh[S_TOK*HID];
__device__ unsigned short g_h1h[S_TOK*HID];
__device__ unsigned short g_mlph[S_TOK*MLP_P2];     // cols 4304..4351 stay zero
__device__ unsigned short g_wqkvth[QKV_N*HID];
__device__ unsigned short g_woth[HID*HID];
__device__ unsigned short g_w1th[MLP_DIM*HID];
__device__ unsigned short g_w2th[HID*MLP_P2];       // k 4304..4351 stay zero

// ---------------- PTX helpers ----------------
__device__ __forceinline__ uint32_t smem_u32(const void* p) {
    uint32_t a;
    asm("{ .reg .u64 t; cvta.to.shared.u64 t, %1; cvt.u32.u64 %0, t; }"
        : "=r"(a) : "l"(p));
    return a;
}

#define MMA_F16(C, A, B0, B1)                                               \
    asm volatile("mma.sync.aligned.m16n8k16.row.col.f32.f16.f16.f32 "       \
                 "{%0,%1,%2,%3}, {%4,%5,%6,%7}, {%8,%9}, {%0,%1,%2,%3};\n"  \
                 : "+f"((C)[0]), "+f"((C)[1]), "+f"((C)[2]), "+f"((C)[3])   \
                 : "r"((A)[0]), "r"((A)[1]), "r"((A)[2]), "r"((A)[3]),      \
                   "r"(B0), "r"(B1))

#define LDSM_X4(R, a)                                                          \
    asm volatile("ldmatrix.sync.aligned.m8n8.x4.shared.b16 {%0,%1,%2,%3}, [%4];" \
                 : "=r"((R)[0]), "=r"((R)[1]), "=r"((R)[2]), "=r"((R)[3])      \
                 : "r"(a))
#define LDSM_X2(R, a)                                                          \
    asm volatile("ldmatrix.sync.aligned.m8n8.x2.shared.b16 {%0,%1}, [%2];"     \
                 : "=r"((R)[0]), "=r"((R)[1]) : "r"(a))

__device__ __forceinline__ void cp_async16(unsigned dst, const void* src, bool valid) {
    int sz = valid ? 16 : 0;
    asm volatile("cp.async.cg.shared.global [%0], [%1], 16, %2;"
                 :: "r"(dst), "l"(src), "r"(sz));
}
#define CP_COMMIT asm volatile("cp.async.commit_group;")
#define CP_WAIT1  asm volatile("cp.async.wait_group 1;")
#define CP_WAIT0  asm volatile("cp.async.wait_group 0;")

__device__ __forceinline__ float gelu_fast(float v) {
    float u = 0.7978845608028654f * (v + 0.044715f * v * v * v);
    return v / (1.0f + __expf(-2.0f * u));
}

// ---------------- LayerNorm (emits fp16 output: feeds GEMM A) --------------
__global__ void ln_kernel(const float* __restrict__ x, const float* __restrict__ g,
                          const float* __restrict__ b, __half* __restrict__ y) {
    __shared__ float row[HID];
    __shared__ float red_s[256], red_ss[256];
    int r = blockIdx.x;
    int tid = threadIdx.x;
    float s = 0.f, ss = 0.f;
    for (int i = tid; i < HID; i += 256) {
        float v = x[(size_t)r*HID + i];
        row[i] = v;
        s += v; ss += v*v;
    }
    red_s[tid] = s; red_ss[tid] = ss;
    __syncthreads();
    for (int o = 128; o > 0; o >>= 1) {
        if (tid < o) { red_s[tid] += red_s[tid+o]; red_ss[tid] += red_ss[tid+o]; }
        __syncthreads();
    }
    float mu = red_s[0] * (1.0f/HID);
    float var = red_ss[0] * (1.0f/HID) - mu*mu;
    float rstd = rsqrtf(var + EPS);
    for (int i = tid; i < HID; i += 256) {
        y[(size_t)r*HID + i] = __float2half_rn((row[i] - mu) * rstd * g[i] + b[i]);
    }
}

// ---------------- weight transpose: [K][N] fp32 -> [N][K(out_ld)] fp16 ------
__global__ void transpose_kernel(const float* __restrict__ in, __half* __restrict__ out,
                                 int K, int N, int out_ld) {
    __shared__ float t[32][33];
    int kb = blockIdx.y*32, nb = blockIdx.x*32;
    int x = threadIdx.x, y = threadIdx.y;   // 32 x 8
#pragma unroll
    for (int i = 0; i < 32; i += 8) {
        int k = kb + y + i, n = nb + x;
        t[y+i][x] = (k < K && n < N) ? in[(size_t)k*N + n] : 0.f;
    }
    __syncthreads();
#pragma unroll
    for (int i = 0; i < 32; i += 8) {
        int n = nb + y + i, k = kb + x;
        if (n < N && k < K) out[(size_t)n*out_ld + k] = __float2half_rn(t[x][y+i]);
    }
}

// ---------------- rope prep: qkvh -> Qr/Kr (rope'd, [h][tok][80]) + Vt ------
// grid (S_TOK/128, NH), 256 threads
#define VS_P 82   // smem V stage stride (halfs): odd-word stride, conflict-safe
__global__ void rope_prep(const __half* __restrict__ qkv, const float* __restrict__ fc,
                          __half* __restrict__ Qr, __half* __restrict__ Kr,
                          __half* __restrict__ Vt) {
    __shared__ __half vs[128*VS_P];
    int tid = threadIdx.x;
    int h = blockIdx.y, t0 = blockIdx.x*128;

    // Q and K rope: 128 rows x 9 chunks of 8 halfs
    for (int t = tid; t < 128*9; t += 256) {
        int row = t/9, ch = t - row*9;
        int tok = t0 + row, d0 = ch*8;
        float4 cA = *(const float4*)&fc[(size_t)tok*HD + d0];
        float4 cB = *(const float4*)&fc[(size_t)tok*HD + d0 + 4];
        // Q
        {
            uint4 raw = *(const uint4*)&qkv[(size_t)tok*QKV_N + h*HD + d0];
            float2 f0 = __half22float2(*(__half2*)&raw.x);
            float2 f1 = __half22float2(*(__half2*)&raw.y);
            float2 f2 = __half22float2(*(__half2*)&raw.z);
            float2 f3 = __half22float2(*(__half2*)&raw.w);
            uint4 o;
            *(__half2*)&o.x = __floats2half2_rn(f0.x*cA.x - f0.y*cA.y, f0.x*cA.y + f0.y*cA.x);
            *(__half2*)&o.y = __floats2half2_rn(f1.x*cA.z - f1.y*cA.w, f1.x*cA.w + f1.y*cA.z);
            *(__half2*)&o.z = __floats2half2_rn(f2.x*cB.x - f2.y*cB.y, f2.x*cB.y + f2.y*cB.x);
            *(__half2*)&o.w = __floats2half2_rn(f3.x*cB.z - f3.y*cB.w, f3.x*cB.w + f3.y*cB.z);
            *(uint4*)&Qr[((size_t)h*S_TOK + tok)*80 + d0] = o;
        }
        // K
        {
            uint4 raw = *(const uint4*)&qkv[(size_t)tok*QKV_N + HID + h*HD + d0];
            float2 f0 = __half22float2(*(__half2*)&raw.x);
            float2 f1 = __half22float2(*(__half2*)&raw.y);
            float2 f2 = __half22float2(*(__half2*)&raw.z);
            float2 f3 = __half22float2(*(__half2*)&raw.w);
            uint4 o;
            *(__half2*)&o.x = __floats2half2_rn(f0.x*cA.x - f0.y*cA.y, f0.x*cA.y + f0.y*cA.x);
            *(__half2*)&o.y = __floats2half2_rn(f1.x*cA.z - f1.y*cA.w, f1.x*cA.w + f1.y*cA.z);
            *(__half2*)&o.z = __floats2half2_rn(f2.x*cB.x - f2.y*cB.y, f2.x*cB.y + f2.y*cB.x);
            *(__half2*)&o.w = __floats2half2_rn(f3.x*cB.z - f3.y*cB.w, f3.x*cB.w + f3.y*cB.z);
            *(uint4*)&Kr[((size_t)h*S_TOK + tok)*80 + d0] = o;
        }
    }
    // pad halfs 72..79 with zeros
    if (tid < 128) {
        int tok = t0 + tid;
        *(uint4*)&Qr[((size_t)h*S_TOK + tok)*80 + 72] = make_uint4(0,0,0,0);
        *(uint4*)&Kr[((size_t)h*S_TOK + tok)*80 + 72] = make_uint4(0,0,0,0);
    }
    // V: stage rows into smem, then write transposed
    for (int t = tid; t < 128*9; t += 256) {
        int row = t/9, ch = t - row*9;
        int d0 = ch*8;
        uint4 raw = *(const uint4*)&qkv[(size_t)(t0+row)*QKV_N + 2*HID + h*HD + d0];
        uint32_t* w = (uint32_t*)&vs[row*VS_P + d0];
        w[0] = raw.x; w[1] = raw.y; w[2] = raw.z; w[3] = raw.w;
    }
    __syncthreads();
    for (int t = tid; t < HD*16; t += 256) {
        int d = t >> 4, cg = t & 15;
        int tok = cg*8;
        __half tmp[8];
#pragma unroll
        for (int i = 0; i < 8; i++) tmp[i] = vs[(tok+i)*VS_P + d];
        *(uint4*)&Vt[((size_t)h*HD + d)*S_TOK + t0 + tok] = *(uint4*)tmp;
    }
}

// ---------------- fp16 GEMM 128x128, 3-stage cp.async (all GEMMs) -----------
// mode 0: bias fp32 out; 1: bias+residual fp32 out; 2: bias+gelu fp16 out;
// mode 3: bias fp16 out
#define GBK 64
#define TILE_B (128*128)
#define STAGE_B (2*TILE_B)
#define NSTAGE 3
#define GEMM_SMEM (NSTAGE*STAGE_B)   // 98304

__global__ void __launch_bounds__(256, 2)
hgemm(const __half* __restrict__ A, int ldA,
      const __half* __restrict__ Bt, int ldB,
      const float* __restrict__ bias, const float* __restrict__ residual,
      void* __restrict__ Cv, int ldC, int N, int NIT, int mode) {
    extern __shared__ char smg[];
    unsigned sbase = smem_u32(smg);
    int tid = threadIdx.x, warp = tid >> 5, lane = tid & 31;
    int g = lane >> 2, tg = lane & 3;
    int wy = warp >> 1, wx = warp & 1;
    int m0 = blockIdx.y*128, n0 = blockIdx.x*128;

    float c[2][8][4];
#pragma unroll
    for (int mt = 0; mt < 2; mt++)
#pragma unroll
        for (int nt = 0; nt < 8; nt++)
#pragma unroll
            for (int i = 0; i < 4; i++) c[mt][nt][i] = 0.f;

    auto stage = [&](int it, int buf) {
        int k0 = it*GBK;
        unsigned sA = sbase + buf*STAGE_B;
        unsigned sB = sA + TILE_B;
#pragma unroll
        for (int i = 0; i < 4; i++) {
            int t = tid + i*256;
            int row = t >> 3, ch = t & 7;
            unsigned off = (unsigned)(row*128) + ((unsigned)(ch ^ (row & 7)) << 4);
            cp_async16(sA + off, A + (size_t)(m0+row)*ldA + k0 + ch*8, true);
            int n = n0 + row;
            bool v = (n < N);
            cp_async16(sB + off, Bt + (size_t)(v ? n : 0)*ldB + k0 + ch*8, v);
        }
    };

    stage(0, 0); CP_COMMIT;
    if (NIT > 1) stage(1, 1);
    CP_COMMIT;

    unsigned hi = (unsigned)(lane >> 4);
    unsigned aoff[2], amask[2], boff[4], bmask[4];
#pragma unroll
    for (int mt = 0; mt < 2; mt++) {
        int r = wy*32 + mt*16 + (lane & 15);
        aoff[mt] = (unsigned)(r*128); amask[mt] = (unsigned)(r & 7);
    }
#pragma unroll
    for (int p = 0; p < 4; p++) {
        int r = wx*64 + p*16 + (lane & 15);
        boff[p] = (unsigned)(r*128); bmask[p] = (unsigned)(r & 7);
    }

    for (int it = 0; it < NIT; it++) {
        CP_WAIT1;
        __syncthreads();
        if (it + 2 < NIT) stage(it+2, (it+2)%NSTAGE);
        CP_COMMIT;
        unsigned sA = sbase + (it%NSTAGE)*STAGE_B;
        unsigned sB = sA + TILE_B;
#pragma unroll
        for (int s = 0; s < 4; s++) {
            unsigned ci = (unsigned)(s*2) + hi;
            unsigned a[2][4], b[4][4];
#pragma unroll
            for (int mt = 0; mt < 2; mt++)
                LDSM_X4(a[mt], sA + aoff[mt] + ((ci ^ amask[mt]) << 4));
#pragma unroll
            for (int p = 0; p < 4; p++)
                LDSM_X4(b[p], sB + boff[p] + ((ci ^ bmask[p]) << 4));
#pragma unroll
            for (int mt = 0; mt < 2; mt++)
#pragma unroll
                for (int p = 0; p < 4; p++) {
                    MMA_F16(c[mt][2*p],   a[mt], b[p][0], b[p][2]);
                    MMA_F16(c[mt][2*p+1], a[mt], b[p][1], b[p][3]);
                }
        }
    }

    float* Cf = (float*)Cv;
    __half* Ch = (__half*)Cv;
#pragma unroll
    for (int mt = 0; mt < 2; mt++) {
        int row0 = m0 + wy*32 + mt*16 + g;
#pragma unroll
        for (int nt = 0; nt < 8; nt++) {
            int col = n0 + wx*64 + nt*8 + tg*2;
            if (col >= N) continue;
#pragma unroll
            for (int hf = 0; hf < 2; hf++) {
                int r = row0 + hf*8;
                float v0 = c[mt][nt][hf*2+0] + bias[col];
                float v1 = c[mt][nt][hf*2+1] + bias[col+1];
                if (mode == 1) {
                    v0 += residual[(size_t)r*ldC + col];
                    v1 += residual[(size_t)r*ldC + col + 1];
                    *(float2*)&Cf[(size_t)r*ldC + col] = make_float2(v0, v1);
                } else if (mode == 2) {
                    *(__half2*)&Ch[(size_t)r*ldC + col] =
                        __floats2half2_rn(gelu_fast(v0), gelu_fast(v1));
                } else if (mode == 3) {
                    *(__half2*)&Ch[(size_t)r*ldC + col] = __floats2half2_rn(v0, v1);
                } else {
                    *(float2*)&Cf[(size_t)r*ldC + col] = make_float2(v0, v1);
                }
            }
        }
    }
}

// ---------------- attention: fp16 MMA, cp.async staging, register softmax ---
#define AQ2 128
#define AK2 64
#define QKS_H 88     // Qs/Ks row stride in halfs (80 used)
#define PVS_H 72     // Ps/Vs row stride in halfs (64 used)

__device__ __forceinline__ int seg_of(int t, const int* offs) {
    int s = 0;
#pragma unroll
    for (int i = 1; i <= 6; i++) if (offs[i] <= t) s = i;
    return s;
}

#define ATTN_SMEM ((AQ2*QKS_H + AK2*QKS_H + HD*PVS_H + AQ2*PVS_H)*2 + (64+8)*4)

__global__ void __launch_bounds__(256)
attn2_kernel(const __half* __restrict__ Qr, const __half* __restrict__ Kr,
             const __half* __restrict__ Vt, const int* __restrict__ offs,
             __half* __restrict__ out) {
    extern __shared__ char sm[];
    __half* Qh = (__half*)sm;
    __half* Kh = Qh + AQ2*QKS_H;
    __half* Vh = Kh + AK2*QKS_H;
    __half* Ph = Vh + HD*PVS_H;
    int* segk  = (int*)(Ph + AQ2*PVS_H);
    int* soffs = segk + 64;

    unsigned sbase = smem_u32(sm);
    unsigned uQ = sbase;
    unsigned uK = uQ + AQ2*QKS_H*2;
    unsigned uV = uK + AK2*QKS_H*2;
    unsigned uP = uV + HD*PVS_H*2;

    int tid = threadIdx.x, warp = tid >> 5, lane = tid & 31;
    int g = lane >> 2, tg = lane & 3;
    int h = blockIdx.y, q0 = blockIdx.x*AQ2;

    if (tid < 7) soffs[tid] = offs[tid];

    // stage Q (rope'd + padded in prep): 128 rows x 10 cp.async chunks
    {
        const __half* qsrc = Qr + ((size_t)h*S_TOK + q0)*80;
        for (int t = tid; t < AQ2*10; t += 256) {
            int row = t/10, ch = t - row*10;
            cp_async16(uQ + (unsigned)(row*QKS_H*2 + ch*16), qsrc + row*80 + ch*8, true);
        }
        CP_COMMIT;
    }
    __syncthreads();   // soffs visible

    int r1 = warp*16 + g, r2 = r1 + 8;
    int sq1 = seg_of(q0 + r1, soffs);
    int sq2 = seg_of(q0 + r2, soffs);

    float m1 = -1e30f, m2 = -1e30f, l1 = 0.f, l2 = 0.f;
    float co[9][4];
#pragma unroll
    for (int nt = 0; nt < 9; nt++)
#pragma unroll
        for (int i = 0; i < 4; i++) co[nt][i] = 0.f;

    unsigned hi = (unsigned)(lane >> 4);
    unsigned offQ = (unsigned)((warp*16 + (lane & 15))*QKS_H*2) + hi*16;
    unsigned offP = (unsigned)((warp*16 + (lane & 15))*PVS_H*2) + hi*16;
    unsigned offK[4], offV[4];
#pragma unroll
    for (int p = 0; p < 4; p++) {
        offK[p] = (unsigned)((p*16 + (lane & 15))*QKS_H*2) + hi*16;
        offV[p] = (unsigned)((p*16 + (lane & 15))*PVS_H*2) + hi*16;
    }
    unsigned offV8 = (unsigned)((64 + (lane & 7))*PVS_H*2) + ((unsigned)((lane >> 3) & 1))*16;

    const float scale = 0.11785113019775793f;   // 1/sqrt(72)

    for (int j0 = 0; j0 < S_TOK; j0 += AK2) {
        __syncthreads();  // prior iter's K/V/P reads done
        // stage K and V via cp.async (no transform needed)
        {
            const __half* ksrc = Kr + ((size_t)h*S_TOK + j0)*80;
            for (int t = tid; t < AK2*10; t += 256) {
                int row = t/10, ch = t - row*10;
                cp_async16(uK + (unsigned)(row*QKS_H*2 + ch*16), ksrc + row*80 + ch*8, true);
            }
            const __half* vsrc = Vt + (size_t)h*HD*S_TOK + j0;
            for (int t = tid; t < HD*8; t += 256) {
                int d = t >> 3, cg = t & 7;
                cp_async16(uV + (unsigned)(d*PVS_H*2 + cg*16), vsrc + (size_t)d*S_TOK + cg*8, true);
            }
        }
        if (tid < 64) segk[tid] = seg_of(j0 + tid, soffs);
        CP_COMMIT;
        CP_WAIT0;
        __syncthreads();

        float sc[8][4];
#pragma unroll
        for (int nt = 0; nt < 8; nt++)
#pragma unroll
            for (int i = 0; i < 4; i++) sc[nt][i] = 0.f;
#pragma unroll
        for (int s = 0; s < 5; s++) {
            unsigned a[4], b[4][4];
            LDSM_X4(a, uQ + offQ + s*32);
#pragma unroll
            for (int p = 0; p < 4; p++) LDSM_X4(b[p], uK + offK[p] + s*32);
#pragma unroll
            for (int p = 0; p < 4; p++) {
                MMA_F16(sc[2*p],   a, b[p][0], b[p][2]);
                MMA_F16(sc[2*p+1], a, b[p][1], b[p][3]);
            }
        }
        float mx1 = -1e30f, mx2 = -1e30f;
#pragma unroll
        for (int nt = 0; nt < 8; nt++) {
            int col = nt*8 + tg*2;
            int k0s = segk[col], k1s = segk[col+1];
            sc[nt][0] = sc[nt][0]*scale + (sq1 == k0s ? 1.f : 0.f);
            sc[nt][1] = sc[nt][1]*scale + (sq1 == k1s ? 1.f : 0.f);
            sc[nt][2] = sc[nt][2]*scale + (sq2 == k0s ? 1.f : 0.f);
            sc[nt][3] = sc[nt][3]*scale + (sq2 == k1s ? 1.f : 0.f);
            mx1 = fmaxf(mx1, fmaxf(sc[nt][0], sc[nt][1]));
            mx2 = fmaxf(mx2, fmaxf(sc[nt][2], sc[nt][3]));
        }
        mx1 = fmaxf(mx1, __shfl_xor_sync(0xffffffffu, mx1, 1, 4));
        mx1 = fmaxf(mx1, __shfl_xor_sync(0xffffffffu, mx1, 2, 4));
        mx2 = fmaxf(mx2, __shfl_xor_sync(0xffffffffu, mx2, 1, 4));
        mx2 = fmaxf(mx2, __shfl_xor_sync(0xffffffffu, mx2, 2, 4));
        float mn1 = fmaxf(m1, mx1), mn2 = fmaxf(m2, mx2);
        float f1 = __expf(m1 - mn1), f2 = __expf(m2 - mn2);
        m1 = mn1; m2 = mn2;
        float s1 = 0.f, s2 = 0.f;
#pragma unroll
        for (int nt = 0; nt < 8; nt++) {
            float p0 = __expf(sc[nt][0] - m1);
            float p1 = __expf(sc[nt][1] - m1);
            float p2 = __expf(sc[nt][2] - m2);
            float p3 = __expf(sc[nt][3] - m2);
            s1 += p0 + p1; s2 += p2 + p3;
            int col = nt*8 + tg*2;
            *(__half2*)&Ph[r1*PVS_H + col] = __floats2half2_rn(p0, p1);
            *(__half2*)&Ph[r2*PVS_H + col] = __floats2half2_rn(p2, p3);
        }
        s1 += __shfl_xor_sync(0xffffffffu, s1, 1, 4);
        s1 += __shfl_xor_sync(0xffffffffu, s1, 2, 4);
        s2 += __shfl_xor_sync(0xffffffffu, s2, 1, 4);
        s2 += __shfl_xor_sync(0xffffffffu, s2, 2, 4);
        l1 = l1*f1 + s1; l2 = l2*f2 + s2;
#pragma unroll
        for (int nt = 0; nt < 9; nt++) {
            co[nt][0] *= f1; co[nt][1] *= f1;
            co[nt][2] *= f2; co[nt][3] *= f2;
        }
        __syncthreads();
#pragma unroll
        for (int s = 0; s < 4; s++) {
            unsigned a[4], b[4][4], b8[2];
            LDSM_X4(a, uP + offP + s*32);
#pragma unroll
            for (int p = 0; p < 4; p++) LDSM_X4(b[p], uV + offV[p] + s*32);
            LDSM_X2(b8, uV + offV8 + s*32);
#pragma unroll
            for (int p = 0; p < 4; p++) {
                MMA_F16(co[2*p],   a, b[p][0], b[p][2]);
                MMA_F16(co[2*p+1], a, b[p][1], b[p][3]);
            }
            MMA_F16(co[8], a, b8[0], b8[1]);
        }
    }

    float i1 = 1.f/l1, i2 = 1.f/l2;
#pragma unroll
    for (int nt = 0; nt < 9; nt++) {
        int d0 = nt*8 + tg*2;
        *(__half2*)&out[(size_t)(q0+r1)*HID + h*HD + d0] =
            __floats2half2_rn(co[nt][0]*i1, co[nt][1]*i1);
        *(__half2*)&out[(size_t)(q0+r2)*HID + h*HD + d0] =
            __floats2half2_rn(co[nt][2]*i2, co[nt][3]*i2);
    }
}

// ---------------- launch ----------------
extern "C" void kernel_launch(void* const* d_in, const int* in_sizes, int n_in,
                              void* d_out, int out_size) {
    const float* x      = (const float*)d_in[0];
    const int*   offs   = (const int*)  d_in[1];
    const float* fc     = (const float*)d_in[2];
    const float* ln0_g  = (const float*)d_in[3];
    const float* ln0_b  = (const float*)d_in[4];
    const float* wqkv_w = (const float*)d_in[5];
    const float* wqkv_b = (const float*)d_in[6];
    const float* wo_w   = (const float*)d_in[7];
    const float* wo_b   = (const float*)d_in[8];
    const float* ln1_g  = (const float*)d_in[9];
    const float* ln1_b  = (const float*)d_in[10];
    const float* w1     = (const float*)d_in[11];
    const float* b1     = (const float*)d_in[12];
    const float* w2     = (const float*)d_in[13];
    const float* b2     = (const float*)d_in[14];
    float* out = (float*)d_out;

    float *x2;
    __half *qkvh, *Qr, *Kr, *Vt, *h0h, *attnh, *h1h, *mlph;
    __half *wqkvth, *woth, *w1th, *w2th;
    cudaGetSymbolAddress((void**)&x2,     g_x2);
    cudaGetSymbolAddress((void**)&qkvh,   g_qkvh);
    cudaGetSymbolAddress((void**)&Qr,     g_Qr);
    cudaGetSymbolAddress((void**)&Kr,     g_Kr);
    cudaGetSymbolAddress((void**)&Vt,     g_Vt);
    cudaGetSymbolAddress((void**)&h0h,    g_h0h);
    cudaGetSymbolAddress((void**)&attnh,  g_attnh);
    cudaGetSymbolAddress((void**)&h1h,    g_h1h);
    cudaGetSymbolAddress((void**)&mlph,   g_mlph);
    cudaGetSymbolAddress((void**)&wqkvth, g_wqkvth);
    cudaGetSymbolAddress((void**)&woth,   g_woth);
    cudaGetSymbolAddress((void**)&w1th,   g_w1th);
    cudaGetSymbolAddress((void**)&w2th,   g_w2th);

    cudaFuncSetAttribute(hgemm, cudaFuncAttributeMaxDynamicSharedMemorySize, GEMM_SMEM);
    cudaFuncSetAttribute(attn2_kernel, cudaFuncAttributeMaxDynamicSharedMemorySize, ATTN_SMEM);

    // 0. transpose weights -> [N][K] fp16
    transpose_kernel<<<dim3((QKV_N+31)/32, (HID+31)/32), dim3(32,8)>>>(wqkv_w, wqkvth, HID, QKV_N, HID);
    transpose_kernel<<<dim3((HID+31)/32, (HID+31)/32),   dim3(32,8)>>>(wo_w,   woth,   HID, HID,   HID);
    transpose_kernel<<<dim3((MLP_DIM+31)/32, (HID+31)/32), dim3(32,8)>>>(w1, w1th, HID, MLP_DIM, HID);
    transpose_kernel<<<dim3((HID+31)/32, (MLP_DIM+31)/32), dim3(32,8)>>>(w2, w2th, MLP_DIM, HID, MLP_P2);

    // 1. LN0 -> fp16
    ln_kernel<<<S_TOK, 256>>>(x, ln0_g, ln0_b, h0h);
    // 2. QKV = h0 @ wqkv + b  -> fp16
    hgemm<<<dim3(QKV_N/128, S_TOK/128), 256, GEMM_SMEM>>>(
        h0h, HID, wqkvth, HID, wqkv_b, nullptr, qkvh, QKV_N, QKV_N, HID/GBK, 3);
    // 3. rope prep: Qr/Kr rope'd + padded, Vt transposed
    rope_prep<<<dim3(S_TOK/128, NH), 256>>>(qkvh, fc, Qr, Kr, Vt);
    // 4. attention -> fp16
    attn2_kernel<<<dim3(S_TOK/AQ2, NH), 256, ATTN_SMEM>>>(Qr, Kr, Vt, offs, attnh);
    // 5. x2 = x + attn @ wo + b  (fp32 out)
    hgemm<<<dim3(HID/128, S_TOK/128), 256, GEMM_SMEM>>>(
        attnh, HID, woth, HID, wo_b, x, x2, HID, HID, HID/GBK, 1);
    // 6. LN1 -> fp16
    ln_kernel<<<S_TOK, 256>>>(x2, ln1_g, ln1_b, h1h);
    // 7. mlp = gelu(h1 @ w1 + b1) -> fp16 (padded ldC)
    hgemm<<<dim3((MLP_DIM+127)/128, S_TOK/128), 256, GEMM_SMEM>>>(
        h1h, HID, w1th, HID, b1, nullptr, mlph, MLP_P2, MLP_DIM, HID/GBK, 2);
    // 8. out = x2 + mlp @ w2 + b2  (K padded to 4352 with zeros)
    hgemm<<<dim3(HID/128, S_TOK/128), 256, GEMM_SMEM>>>(
        mlph, MLP_P2, w2th, MLP_P2, b2, x2, out, HID, HID, MLP_P2/GBK, 1);
}

// round 14
// speedup vs baseline: 1.4742x; 1.0265x over previous
#include <cuda_runtime.h>
#include <cuda_bf16.h>
#include <cuda_fp16.h>
#include <stdint.h>
#include <math.h>

// Problem constants
#define S_TOK 3072
#define HID 1152
#define NH 16
#define HD 72
#define MLP_DIM 4304
#define MLP_P2 4352           // MLP_DIM padded to multiple of 64 (zeros in pad)
#define QKV_N (3*HID)         // 3456
#define EPS 1e-5f

// ---------------- scratch (allocation-free: __device__ globals, zero-init) ----
__device__ float g_x2[S_TOK*HID];
__device__ unsigned short g_qkvh[S_TOK*QKV_N];      // fp16 qkv (pre-rope)
__device__ unsigned short g_Qr[NH*S_TOK*80];        // rope'd Q, [h][tok][80]
__device__ unsigned short g_Kr[NH*S_TOK*80];        // rope'd K, [h][tok][80]
__device__ unsigned short g_Vt[NH*HD*S_TOK];        // V^T,     [h][d][tok]
__device__ unsigned short g_h0h[S_TOK*HID];
__device__ unsigned short g_attnh[S_TOK*HID];
__device__ unsigned short g_h1h[S_TOK*HID];
__device__ unsigned short g_mlph[S_TOK*MLP_P2];     // cols 4304..4351 stay zero
__device__ unsigned short g_wqkvth[QKV_N*HID];
__device__ unsigned short g_woth[HID*HID];
__device__ unsigned short g_w1th[MLP_DIM*HID];
__device__ unsigned short g_w2th[HID*MLP_P2];       // k 4304..4351 stay zero

// ---------------- PTX helpers ----------------
__device__ __forceinline__ uint32_t smem_u32(const void* p) {
    uint32_t a;
    asm("{ .reg .u64 t; cvta.to.shared.u64 t, %1; cvt.u32.u64 %0, t; }"
        : "=r"(a) : "l"(p));
    return a;
}

#define MMA_F16(C, A, B0, B1)                                               \
    asm volatile("mma.sync.aligned.m16n8k16.row.col.f32.f16.f16.f32 "       \
                 "{%0,%1,%2,%3}, {%4,%5,%6,%7}, {%8,%9}, {%0,%1,%2,%3};\n"  \
                 : "+f"((C)[0]), "+f"((C)[1]), "+f"((C)[2]), "+f"((C)[3])   \
                 : "r"((A)[0]), "r"((A)[1]), "r"((A)[2]), "r"((A)[3]),      \
                   "r"(B0), "r"(B1))

#define LDSM_X4(R, a)                                                          \
    asm volatile("ldmatrix.sync.aligned.m8n8.x4.shared.b16 {%0,%1,%2,%3}, [%4];" \
                 : "=r"((R)[0]), "=r"((R)[1]), "=r"((R)[2]), "=r"((R)[3])      \
                 : "r"(a))
#define LDSM_X2(R, a)                                                          \
    asm volatile("ldmatrix.sync.aligned.m8n8.x2.shared.b16 {%0,%1}, [%2];"     \
                 : "=r"((R)[0]), "=r"((R)[1]) : "r"(a))

__device__ __forceinline__ void cp_async16(unsigned dst, const void* src, bool valid) {
    int sz = valid ? 16 : 0;
    asm volatile("cp.async.cg.shared.global [%0], [%1], 16, %2;"
                 :: "r"(dst), "l"(src), "r"(sz));
}
#define CP_COMMIT asm volatile("cp.async.commit_group;")
#define CP_WAIT1  asm volatile("cp.async.wait_group 1;")
#define CP_WAIT0  asm volatile("cp.async.wait_group 0;")

__device__ __forceinline__ float gelu_fast(float v) {
    float u = 0.7978845608028654f * (v + 0.044715f * v * v * v);
    return v / (1.0f + __expf(-2.0f * u));
}

// ---------------- LayerNorm (warp-shuffle reduce, fp16 out) -----------------
__global__ void ln_kernel(const float* __restrict__ x, const float* __restrict__ g,
                          const float* __restrict__ b, __half* __restrict__ y) {
    __shared__ float row[HID];
    __shared__ float ws[8], wss[8], bc[2];
    int r = blockIdx.x;
    int tid = threadIdx.x, lane = tid & 31, warp = tid >> 5;
    float s = 0.f, ss = 0.f;
    for (int i = tid; i < HID; i += 256) {
        float v = x[(size_t)r*HID + i];
        row[i] = v;
        s += v; ss += v*v;
    }
#pragma unroll
    for (int o = 16; o > 0; o >>= 1) {
        s  += __shfl_xor_sync(0xffffffffu, s, o);
        ss += __shfl_xor_sync(0xffffffffu, ss, o);
    }
    if (lane == 0) { ws[warp] = s; wss[warp] = ss; }
    __syncthreads();
    if (warp == 0) {
        float a = (lane < 8) ? ws[lane] : 0.f;
        float c = (lane < 8) ? wss[lane] : 0.f;
#pragma unroll
        for (int o = 4; o > 0; o >>= 1) {
            a += __shfl_xor_sync(0xffffffffu, a, o, 8);
            c += __shfl_xor_sync(0xffffffffu, c, o, 8);
        }
        if (lane == 0) {
            float mu = a * (1.0f/HID);
            float var = c * (1.0f/HID) - mu*mu;
            bc[0] = mu; bc[1] = rsqrtf(var + EPS);
        }
    }
    __syncthreads();
    float mu = bc[0], rstd = bc[1];
    for (int i = tid; i < HID; i += 256) {
        y[(size_t)r*HID + i] = __float2half_rn((row[i] - mu) * rstd * g[i] + b[i]);
    }
}

// ---------------- weight transpose: [K][N] fp32 -> [N][K(out_ld)] fp16 ------
__global__ void transpose_kernel(const float* __restrict__ in, __half* __restrict__ out,
                                 int K, int N, int out_ld) {
    __shared__ float t[32][33];
    int kb = blockIdx.y*32, nb = blockIdx.x*32;
    int x = threadIdx.x, y = threadIdx.y;   // 32 x 8
#pragma unroll
    for (int i = 0; i < 32; i += 8) {
        int k = kb + y + i, n = nb + x;
        t[y+i][x] = (k < K && n < N) ? in[(size_t)k*N + n] : 0.f;
    }
    __syncthreads();
#pragma unroll
    for (int i = 0; i < 32; i += 8) {
        int n = nb + y + i, k = kb + x;
        if (n < N && k < K) out[(size_t)n*out_ld + k] = __float2half_rn(t[x][y+i]);
    }
}

// ---------------- rope prep: qkvh -> Qr/Kr (rope'd, [h][tok][80]) + Vt ------
#define VS_P 82
__global__ void rope_prep(const __half* __restrict__ qkv, const float* __restrict__ fc,
                          __half* __restrict__ Qr, __half* __restrict__ Kr,
                          __half* __restrict__ Vt) {
    __shared__ __half vs[128*VS_P];
    int tid = threadIdx.x;
    int h = blockIdx.y, t0 = blockIdx.x*128;

    for (int t = tid; t < 128*9; t += 256) {
        int row = t/9, ch = t - row*9;
        int tok = t0 + row, d0 = ch*8;
        float4 cA = *(const float4*)&fc[(size_t)tok*HD + d0];
        float4 cB = *(const float4*)&fc[(size_t)tok*HD + d0 + 4];
        {
            uint4 raw = *(const uint4*)&qkv[(size_t)tok*QKV_N + h*HD + d0];
            float2 f0 = __half22float2(*(__half2*)&raw.x);
            float2 f1 = __half22float2(*(__half2*)&raw.y);
            float2 f2 = __half22float2(*(__half2*)&raw.z);
            float2 f3 = __half22float2(*(__half2*)&raw.w);
            uint4 o;
            *(__half2*)&o.x = __floats2half2_rn(f0.x*cA.x - f0.y*cA.y, f0.x*cA.y + f0.y*cA.x);
            *(__half2*)&o.y = __floats2half2_rn(f1.x*cA.z - f1.y*cA.w, f1.x*cA.w + f1.y*cA.z);
            *(__half2*)&o.z = __floats2half2_rn(f2.x*cB.x - f2.y*cB.y, f2.x*cB.y + f2.y*cB.x);
            *(__half2*)&o.w = __floats2half2_rn(f3.x*cB.z - f3.y*cB.w, f3.x*cB.w + f3.y*cB.z);
            *(uint4*)&Qr[((size_t)h*S_TOK + tok)*80 + d0] = o;
        }
        {
            uint4 raw = *(const uint4*)&qkv[(size_t)tok*QKV_N + HID + h*HD + d0];
            float2 f0 = __half22float2(*(__half2*)&raw.x);
            float2 f1 = __half22float2(*(__half2*)&raw.y);
            float2 f2 = __half22float2(*(__half2*)&raw.z);
            float2 f3 = __half22float2(*(__half2*)&raw.w);
            uint4 o;
            *(__half2*)&o.x = __floats2half2_rn(f0.x*cA.x - f0.y*cA.y, f0.x*cA.y + f0.y*cA.x);
            *(__half2*)&o.y = __floats2half2_rn(f1.x*cA.z - f1.y*cA.w, f1.x*cA.w + f1.y*cA.z);
            *(__half2*)&o.z = __floats2half2_rn(f2.x*cB.x - f2.y*cB.y, f2.x*cB.y + f2.y*cB.x);
            *(__half2*)&o.w = __floats2half2_rn(f3.x*cB.z - f3.y*cB.w, f3.x*cB.w + f3.y*cB.z);
            *(uint4*)&Kr[((size_t)h*S_TOK + tok)*80 + d0] = o;
        }
    }
    if (tid < 128) {
        int tok = t0 + tid;
        *(uint4*)&Qr[((size_t)h*S_TOK + tok)*80 + 72] = make_uint4(0,0,0,0);
        *(uint4*)&Kr[((size_t)h*S_TOK + tok)*80 + 72] = make_uint4(0,0,0,0);
    }
    for (int t = tid; t < 128*9; t += 256) {
        int row = t/9, ch = t - row*9;
        int d0 = ch*8;
        uint4 raw = *(const uint4*)&qkv[(size_t)(t0+row)*QKV_N + 2*HID + h*HD + d0];
        uint32_t* w = (uint32_t*)&vs[row*VS_P + d0];
        w[0] = raw.x; w[1] = raw.y; w[2] = raw.z; w[3] = raw.w;
    }
    __syncthreads();
    for (int t = tid; t < HD*16; t += 256) {
        int d = t >> 4, cg = t & 15;
        int tok = cg*8;
        __half tmp[8];
#pragma unroll
        for (int i = 0; i < 8; i++) tmp[i] = vs[(tok+i)*VS_P + d];
        *(uint4*)&Vt[((size_t)h*HD + d)*S_TOK + t0 + tok] = *(uint4*)tmp;
    }
}

// ---------------- fp16 GEMM 128x128, 3-stage cp.async (all GEMMs) -----------
#define GBK 64
#define TILE_B (128*128)
#define STAGE_B (2*TILE_B)
#define NSTAGE 3
#define GEMM_SMEM (NSTAGE*STAGE_B)   // 98304

__global__ void __launch_bounds__(256, 2)
hgemm(const __half* __restrict__ A, int ldA,
      const __half* __restrict__ Bt, int ldB,
      const float* __restrict__ bias, const float* __restrict__ residual,
      void* __restrict__ Cv, int ldC, int N, int NIT, int mode) {
    extern __shared__ char smg[];
    unsigned sbase = smem_u32(smg);
    int tid = threadIdx.x, warp = tid >> 5, lane = tid & 31;
    int g = lane >> 2, tg = lane & 3;
    int wy = warp >> 1, wx = warp & 1;
    int m0 = blockIdx.y*128, n0 = blockIdx.x*128;

    float c[2][8][4];
#pragma unroll
    for (int mt = 0; mt < 2; mt++)
#pragma unroll
        for (int nt = 0; nt < 8; nt++)
#pragma unroll
            for (int i = 0; i < 4; i++) c[mt][nt][i] = 0.f;

    auto stage = [&](int it, int buf) {
        int k0 = it*GBK;
        unsigned sA = sbase + buf*STAGE_B;
        unsigned sB = sA + TILE_B;
#pragma unroll
        for (int i = 0; i < 4; i++) {
            int t = tid + i*256;
            int row = t >> 3, ch = t & 7;
            unsigned off = (unsigned)(row*128) + ((unsigned)(ch ^ (row & 7)) << 4);
            cp_async16(sA + off, A + (size_t)(m0+row)*ldA + k0 + ch*8, true);
            int n = n0 + row;
            bool v = (n < N);
            cp_async16(sB + off, Bt + (size_t)(v ? n : 0)*ldB + k0 + ch*8, v);
        }
    };

    stage(0, 0); CP_COMMIT;
    if (NIT > 1) stage(1, 1);
    CP_COMMIT;

    unsigned hi = (unsigned)(lane >> 4);
    unsigned aoff[2], amask[2], boff[4], bmask[4];
#pragma unroll
    for (int mt = 0; mt < 2; mt++) {
        int r = wy*32 + mt*16 + (lane & 15);
        aoff[mt] = (unsigned)(r*128); amask[mt] = (unsigned)(r & 7);
    }
#pragma unroll
    for (int p = 0; p < 4; p++) {
        int r = wx*64 + p*16 + (lane & 15);
        boff[p] = (unsigned)(r*128); bmask[p] = (unsigned)(r & 7);
    }

    for (int it = 0; it < NIT; it++) {
        CP_WAIT1;
        __syncthreads();
        if (it + 2 < NIT) stage(it+2, (it+2)%NSTAGE);
        CP_COMMIT;
        unsigned sA = sbase + (it%NSTAGE)*STAGE_B;
        unsigned sB = sA + TILE_B;
#pragma unroll
        for (int s = 0; s < 4; s++) {
            unsigned ci = (unsigned)(s*2) + hi;
            unsigned a[2][4], b[4][4];
#pragma unroll
            for (int mt = 0; mt < 2; mt++)
                LDSM_X4(a[mt], sA + aoff[mt] + ((ci ^ amask[mt]) << 4));
#pragma unroll
            for (int p = 0; p < 4; p++)
                LDSM_X4(b[p], sB + boff[p] + ((ci ^ bmask[p]) << 4));
#pragma unroll
            for (int mt = 0; mt < 2; mt++)
#pragma unroll
                for (int p = 0; p < 4; p++) {
                    MMA_F16(c[mt][2*p],   a[mt], b[p][0], b[p][2]);
                    MMA_F16(c[mt][2*p+1], a[mt], b[p][1], b[p][3]);
                }
        }
    }

    float* Cf = (float*)Cv;
    __half* Ch = (__half*)Cv;
#pragma unroll
    for (int mt = 0; mt < 2; mt++) {
        int row0 = m0 + wy*32 + mt*16 + g;
#pragma unroll
        for (int nt = 0; nt < 8; nt++) {
            int col = n0 + wx*64 + nt*8 + tg*2;
            if (col >= N) continue;
#pragma unroll
            for (int hf = 0; hf < 2; hf++) {
                int r = row0 + hf*8;
                float v0 = c[mt][nt][hf*2+0] + bias[col];
                float v1 = c[mt][nt][hf*2+1] + bias[col+1];
                if (mode == 1) {
                    v0 += residual[(size_t)r*ldC + col];
                    v1 += residual[(size_t)r*ldC + col + 1];
                    *(float2*)&Cf[(size_t)r*ldC + col] = make_float2(v0, v1);
                } else if (mode == 2) {
                    *(__half2*)&Ch[(size_t)r*ldC + col] =
                        __floats2half2_rn(gelu_fast(v0), gelu_fast(v1));
                } else if (mode == 3) {
                    *(__half2*)&Ch[(size_t)r*ldC + col] = __floats2half2_rn(v0, v1);
                } else {
                    *(float2*)&Cf[(size_t)r*ldC + col] = make_float2(v0, v1);
                }
            }
        }
    }
}

// ---------------- attention: double-buffered K/V prefetch -------------------
#define AQ2 128
#define AK2 64
#define QKS_H 88     // Qs/Ks row stride in halfs (80 used)
#define PVS_H 72     // Ps/Vs row stride in halfs (64 used)
#define KBUF_H (AK2*QKS_H)      // 5632 halfs per K buffer
#define VBUF_H (HD*PVS_H)       // 5184 halfs per V buffer

__device__ __forceinline__ int seg_of(int t, const int* offs) {
    int s = 0;
#pragma unroll
    for (int i = 1; i <= 6; i++) if (offs[i] <= t) s = i;
    return s;
}

#define ATTN_SMEM ((AQ2*QKS_H + 2*KBUF_H + 2*VBUF_H + AQ2*PVS_H)*2 + (64+8)*4)

__global__ void __launch_bounds__(256)
attn2_kernel(const __half* __restrict__ Qr, const __half* __restrict__ Kr,
             const __half* __restrict__ Vt, const int* __restrict__ offs,
             __half* __restrict__ out) {
    extern __shared__ char sm[];
    __half* Qh = (__half*)sm;
    __half* Ph = Qh + AQ2*QKS_H + 2*KBUF_H + 2*VBUF_H;
    int* segk  = (int*)(Ph + AQ2*PVS_H);
    int* soffs = segk + 64;

    unsigned sbase = smem_u32(sm);
    unsigned uQ = sbase;
    unsigned uK = uQ + AQ2*QKS_H*2;          // 2 buffers, each KBUF_H*2 bytes
    unsigned uV = uK + 2*KBUF_H*2;           // 2 buffers, each VBUF_H*2 bytes
    unsigned uP = uV + 2*VBUF_H*2;

    int tid = threadIdx.x, warp = tid >> 5, lane = tid & 31;
    int g = lane >> 2, tg = lane & 3;
    int h = blockIdx.y, q0 = blockIdx.x*AQ2;

    if (tid < 7) soffs[tid] = offs[tid];

    auto stageKV = [&](int j0, int buf) {
        const __half* ksrc = Kr + ((size_t)h*S_TOK + j0)*80;
        unsigned kd = uK + (unsigned)buf*KBUF_H*2;
        for (int t = tid; t < AK2*10; t += 256) {
            int row = t/10, ch = t - row*10;
            cp_async16(kd + (unsigned)(row*QKS_H*2 + ch*16), ksrc + row*80 + ch*8, true);
        }
        const __half* vsrc = Vt + (size_t)h*HD*S_TOK + j0;
        unsigned vd = uV + (unsigned)buf*VBUF_H*2;
        for (int t = tid; t < HD*8; t += 256) {
            int d = t >> 3, cg = t & 7;
            cp_async16(vd + (unsigned)(d*PVS_H*2 + cg*16), vsrc + (size_t)d*S_TOK + cg*8, true);
        }
    };

    // group 0: Q tile + K/V tile 0
    {
        const __half* qsrc = Qr + ((size_t)h*S_TOK + q0)*80;
        for (int t = tid; t < AQ2*10; t += 256) {
            int row = t/10, ch = t - row*10;
            cp_async16(uQ + (unsigned)(row*QKS_H*2 + ch*16), qsrc + row*80 + ch*8, true);
        }
        stageKV(0, 0);
        CP_COMMIT;
    }
    __syncthreads();   // soffs visible

    int r1 = warp*16 + g, r2 = r1 + 8;
    int sq1 = seg_of(q0 + r1, soffs);
    int sq2 = seg_of(q0 + r2, soffs);

    float m1 = -1e30f, m2 = -1e30f, l1 = 0.f, l2 = 0.f;
    float co[9][4];
#pragma unroll
    for (int nt = 0; nt < 9; nt++)
#pragma unroll
        for (int i = 0; i < 4; i++) co[nt][i] = 0.f;

    unsigned hi = (unsigned)(lane >> 4);
    unsigned offQ = (unsigned)((warp*16 + (lane & 15))*QKS_H*2) + hi*16;
    unsigned offP = (unsigned)((warp*16 + (lane & 15))*PVS_H*2) + hi*16;
    unsigned offK[4], offV[4];
#pragma unroll
    for (int p = 0; p < 4; p++) {
        offK[p] = (unsigned)((p*16 + (lane & 15))*QKS_H*2) + hi*16;
        offV[p] = (unsigned)((p*16 + (lane & 15))*PVS_H*2) + hi*16;
    }
    unsigned offV8 = (unsigned)((64 + (lane & 7))*PVS_H*2) + ((unsigned)((lane >> 3) & 1))*16;

    const float scale = 0.11785113019775793f;   // 1/sqrt(72)
    const int NIT = S_TOK/AK2;

    for (int it = 0; it < NIT; it++) {
        int j0 = it*AK2;
        int b0 = it & 1, b1 = b0 ^ 1;
        __syncthreads();                       // prev compute done (frees buf b1, segk)
        if (it + 1 < NIT) stageKV(j0 + AK2, b1);
        if (tid < 64) segk[tid] = seg_of(j0 + tid, soffs);
        CP_COMMIT;
        CP_WAIT1;                              // group `it` (buf b0) complete
        __syncthreads();                       // visibility

        unsigned uKb = uK + (unsigned)b0*KBUF_H*2;
        unsigned uVb = uV + (unsigned)b0*VBUF_H*2;

        float sc[8][4];
#pragma unroll
        for (int nt = 0; nt < 8; nt++)
#pragma unroll
            for (int i = 0; i < 4; i++) sc[nt][i] = 0.f;
#pragma unroll
        for (int s = 0; s < 5; s++) {
            unsigned a[4], b[4][4];
            LDSM_X4(a, uQ + offQ + s*32);
#pragma unroll
            for (int p = 0; p < 4; p++) LDSM_X4(b[p], uKb + offK[p] + s*32);
#pragma unroll
            for (int p = 0; p < 4; p++) {
                MMA_F16(sc[2*p],   a, b[p][0], b[p][2]);
                MMA_F16(sc[2*p+1], a, b[p][1], b[p][3]);
            }
        }
        float mx1 = -1e30f, mx2 = -1e30f;
#pragma unroll
        for (int nt = 0; nt < 8; nt++) {
            int col = nt*8 + tg*2;
            int k0s = segk[col], k1s = segk[col+1];
            sc[nt][0] = sc[nt][0]*scale + (sq1 == k0s ? 1.f : 0.f);
            sc[nt][1] = sc[nt][1]*scale + (sq1 == k1s ? 1.f : 0.f);
            sc[nt][2] = sc[nt][2]*scale + (sq2 == k0s ? 1.f : 0.f);
            sc[nt][3] = sc[nt][3]*scale + (sq2 == k1s ? 1.f : 0.f);
            mx1 = fmaxf(mx1, fmaxf(sc[nt][0], sc[nt][1]));
            mx2 = fmaxf(mx2, fmaxf(sc[nt][2], sc[nt][3]));
        }
        mx1 = fmaxf(mx1, __shfl_xor_sync(0xffffffffu, mx1, 1, 4));
        mx1 = fmaxf(mx1, __shfl_xor_sync(0xffffffffu, mx1, 2, 4));
        mx2 = fmaxf(mx2, __shfl_xor_sync(0xffffffffu, mx2, 1, 4));
        mx2 = fmaxf(mx2, __shfl_xor_sync(0xffffffffu, mx2, 2, 4));
        float mn1 = fmaxf(m1, mx1), mn2 = fmaxf(m2, mx2);
        float f1 = __expf(m1 - mn1), f2 = __expf(m2 - mn2);
        m1 = mn1; m2 = mn2;
        float s1 = 0.f, s2 = 0.f;
#pragma unroll
        for (int nt = 0; nt < 8; nt++) {
            float p0 = __expf(sc[nt][0] - m1);
            float p1 = __expf(sc[nt][1] - m1);
            float p2 = __expf(sc[nt][2] - m2);
            float p3 = __expf(sc[nt][3] - m2);
            s1 += p0 + p1; s2 += p2 + p3;
            int col = nt*8 + tg*2;
            *(__half2*)&Ph[r1*PVS_H + col] = __floats2half2_rn(p0, p1);
            *(__half2*)&Ph[r2*PVS_H + col] = __floats2half2_rn(p2, p3);
        }
        s1 += __shfl_xor_sync(0xffffffffu, s1, 1, 4);
        s1 += __shfl_xor_sync(0xffffffffu, s1, 2, 4);
        s2 += __shfl_xor_sync(0xffffffffu, s2, 1, 4);
        s2 += __shfl_xor_sync(0xffffffffu, s2, 2, 4);
        l1 = l1*f1 + s1; l2 = l2*f2 + s2;
#pragma unroll
        for (int nt = 0; nt < 9; nt++) {
            co[nt][0] *= f1; co[nt][1] *= f1;
            co[nt][2] *= f2; co[nt][3] *= f2;
        }
        __syncthreads();                       // P visible
#pragma unroll
        for (int s = 0; s < 4; s++) {
            unsigned a[4], b[4][4], b8[2];
            LDSM_X4(a, uP + offP + s*32);
#pragma unroll
            for (int p = 0; p < 4; p++) LDSM_X4(b[p], uVb + offV[p] + s*32);
            LDSM_X2(b8, uVb + offV8 + s*32);
#pragma unroll
            for (int p = 0; p < 4; p++) {
                MMA_F16(co[2*p],   a, b[p][0], b[p][2]);
                MMA_F16(co[2*p+1], a, b[p][1], b[p][3]);
            }
            MMA_F16(co[8], a, b8[0], b8[1]);
        }
    }

    float i1 = 1.f/l1, i2 = 1.f/l2;
#pragma unroll
    for (int nt = 0; nt < 9; nt++) {
        int d0 = nt*8 + tg*2;
        *(__half2*)&out[(size_t)(q0+r1)*HID + h*HD + d0] =
            __floats2half2_rn(co[nt][0]*i1, co[nt][1]*i1);
        *(__half2*)&out[(size_t)(q0+r2)*HID + h*HD + d0] =
            __floats2half2_rn(co[nt][2]*i2, co[nt][3]*i2);
    }
}

// ---------------- launch ----------------
extern "C" void kernel_launch(void* const* d_in, const int* in_sizes, int n_in,
                              void* d_out, int out_size) {
    const float* x      = (const float*)d_in[0];
    const int*   offs   = (const int*)  d_in[1];
    const float* fc     = (const float*)d_in[2];
    const float* ln0_g  = (const float*)d_in[3];
    const float* ln0_b  = (const float*)d_in[4];
    const float* wqkv_w = (const float*)d_in[5];
    const float* wqkv_b = (const float*)d_in[6];
    const float* wo_w   = (const float*)d_in[7];
    const float* wo_b   = (const float*)d_in[8];
    const float* ln1_g  = (const float*)d_in[9];
    const float* ln1_b  = (const float*)d_in[10];
    const float* w1     = (const float*)d_in[11];
    const float* b1     = (const float*)d_in[12];
    const float* w2     = (const float*)d_in[13];
    const float* b2     = (const float*)d_in[14];
    float* out = (float*)d_out;

    float *x2;
    __half *qkvh, *Qr, *Kr, *Vt, *h0h, *attnh, *h1h, *mlph;
    __half *wqkvth, *woth, *w1th, *w2th;
    cudaGetSymbolAddress((void**)&x2,     g_x2);
    cudaGetSymbolAddress((void**)&qkvh,   g_qkvh);
    cudaGetSymbolAddress((void**)&Qr,     g_Qr);
    cudaGetSymbolAddress((void**)&Kr,     g_Kr);
    cudaGetSymbolAddress((void**)&Vt,     g_Vt);
    cudaGetSymbolAddress((void**)&h0h,    g_h0h);
    cudaGetSymbolAddress((void**)&attnh,  g_attnh);
    cudaGetSymbolAddress((void**)&h1h,    g_h1h);
    cudaGetSymbolAddress((void**)&mlph,   g_mlph);
    cudaGetSymbolAddress((void**)&wqkvth, g_wqkvth);
    cudaGetSymbolAddress((void**)&woth,   g_woth);
    cudaGetSymbolAddress((void**)&w1th,   g_w1th);
    cudaGetSymbolAddress((void**)&w2th,   g_w2th);

    cudaFuncSetAttribute(hgemm, cudaFuncAttributeMaxDynamicSharedMemorySize, GEMM_SMEM);
    cudaFuncSetAttribute(attn2_kernel, cudaFuncAttributeMaxDynamicSharedMemorySize, ATTN_SMEM);

    // 0. transpose weights -> [N][K] fp16
    transpose_kernel<<<dim3((QKV_N+31)/32, (HID+31)/32), dim3(32,8)>>>(wqkv_w, wqkvth, HID, QKV_N, HID);
    transpose_kernel<<<dim3((HID+31)/32, (HID+31)/32),   dim3(32,8)>>>(wo_w,   woth,   HID, HID,   HID);
    transpose_kernel<<<dim3((MLP_DIM+31)/32, (HID+31)/32), dim3(32,8)>>>(w1, w1th, HID, MLP_DIM, HID);
    transpose_kernel<<<dim3((HID+31)/32, (MLP_DIM+31)/32), dim3(32,8)>>>(w2, w2th, MLP_DIM, HID, MLP_P2);

    // 1. LN0 -> fp16
    ln_kernel<<<S_TOK, 256>>>(x, ln0_g, ln0_b, h0h);
    // 2. QKV = h0 @ wqkv + b  -> fp16
    hgemm<<<dim3(QKV_N/128, S_TOK/128), 256, GEMM_SMEM>>>(
        h0h, HID, wqkvth, HID, wqkv_b, nullptr, qkvh, QKV_N, QKV_N, HID/GBK, 3);
    // 3. rope prep: Qr/Kr rope'd + padded, Vt transposed
    rope_prep<<<dim3(S_TOK/128, NH), 256>>>(qkvh, fc, Qr, Kr, Vt);
    // 4. attention -> fp16
    attn2_kernel<<<dim3(S_TOK/AQ2, NH), 256, ATTN_SMEM>>>(Qr, Kr, Vt, offs, attnh);
    // 5. x2 = x + attn @ wo + b  (fp32 out)
    hgemm<<<dim3(HID/128, S_TOK/128), 256, GEMM_SMEM>>>(
        attnh, HID, woth, HID, wo_b, x, x2, HID, HID, HID/GBK, 1);
    // 6. LN1 -> fp16
    ln_kernel<<<S_TOK, 256>>>(x2, ln1_g, ln1_b, h1h);
    // 7. mlp = gelu(h1 @ w1 + b1) -> fp16 (padded ldC)
    hgemm<<<dim3((MLP_DIM+127)/128, S_TOK/128), 256, GEMM_SMEM>>>(
        h1h, HID, w1th, HID, b1, nullptr, mlph, MLP_P2, MLP_DIM, HID/GBK, 2);
    // 8. out = x2 + mlp @ w2 + b2  (K padded to 4352 with zeros)
    hgemm<<<dim3(HID/128, S_TOK/128), 256, GEMM_SMEM>>>(
        mlph, MLP_P2, w2th, MLP_P2, b2, x2, out, HID, HID, MLP_P2/GBK, 1);
}